// round 2
// baseline (speedup 1.0000x reference)
#include <cuda_runtime.h>

// Problem constants
#define BB 2
#define NN 2048
#define DDIM 1024
#define HH 16
#define HD 64
#define MROWS (BB * NN)   // 4096
#define N3D (3 * DDIM)    // 3072

// Scratch (no allocations allowed). 128B-aligned for vectorized access.
__device__ __align__(128) float g_qkv[MROWS * N3D];   // [4096, 3072]
__device__ __align__(128) float g_ao[MROWS * DDIM];   // [4096, 1024]

// ---------------------------------------------------------------------------
// SGEMM: C[M,N] = A[M,K] @ W[K,N] + bias[N]
// 128x128 tile, BK=16, 256 threads, 8x8 per-thread microtile.
// ---------------------------------------------------------------------------
template<int M, int N, int K>
__device__ __forceinline__ void sgemm_body(
    const float* __restrict__ A, const float* __restrict__ W,
    const float* __restrict__ bias, float* __restrict__ C)
{
    constexpr int BM = 128, BN = 128, BK = 16;
    __shared__ float As[BK][BM];   // A tile transposed: [k][m]
    __shared__ float Bs[BK][BN];   // W tile: [k][n]

    const int tid = threadIdx.x;
    const int bm = blockIdx.y * BM;
    const int bn = blockIdx.x * BN;
    const int tx = tid & 15;
    const int ty = tid >> 4;

    // load mapping
    const int arow = tid >> 2;          // 0..63 (+64)
    const int acol = (tid & 3) << 2;    // 0,4,8,12
    const int brow = tid >> 5;          // 0..7 (+8)
    const int bcol = (tid & 31) << 2;   // 0..124

    float acc[8][8];
    #pragma unroll
    for (int i = 0; i < 8; i++)
        #pragma unroll
        for (int j = 0; j < 8; j++) acc[i][j] = 0.f;

    for (int k0 = 0; k0 < K; k0 += BK) {
        #pragma unroll
        for (int i = 0; i < 2; i++) {
            int r = arow + i * 64;
            float4 v = *(const float4*)&A[(size_t)(bm + r) * K + k0 + acol];
            As[acol + 0][r] = v.x;
            As[acol + 1][r] = v.y;
            As[acol + 2][r] = v.z;
            As[acol + 3][r] = v.w;
        }
        #pragma unroll
        for (int i = 0; i < 2; i++) {
            int r = brow + i * 8;
            *(float4*)&Bs[r][bcol] =
                *(const float4*)&W[(size_t)(k0 + r) * N + bn + bcol];
        }
        __syncthreads();

        #pragma unroll
        for (int kk = 0; kk < BK; kk++) {
            float a[8], b[8];
            *(float4*)&a[0] = *(const float4*)&As[kk][ty * 8];
            *(float4*)&a[4] = *(const float4*)&As[kk][ty * 8 + 4];
            *(float4*)&b[0] = *(const float4*)&Bs[kk][tx * 8];
            *(float4*)&b[4] = *(const float4*)&Bs[kk][tx * 8 + 4];
            #pragma unroll
            for (int i = 0; i < 8; i++)
                #pragma unroll
                for (int j = 0; j < 8; j++)
                    acc[i][j] += a[i] * b[j];
        }
        __syncthreads();
    }

    float bb[8];
    *(float4*)&bb[0] = *(const float4*)&bias[bn + tx * 8];
    *(float4*)&bb[4] = *(const float4*)&bias[bn + tx * 8 + 4];
    #pragma unroll
    for (int i = 0; i < 8; i++) {
        int row = bm + ty * 8 + i;
        #pragma unroll
        for (int j0 = 0; j0 < 8; j0 += 4) {
            float4 o;
            o.x = acc[i][j0 + 0] + bb[j0 + 0];
            o.y = acc[i][j0 + 1] + bb[j0 + 1];
            o.z = acc[i][j0 + 2] + bb[j0 + 2];
            o.w = acc[i][j0 + 3] + bb[j0 + 3];
            *(float4*)&C[(size_t)row * N + bn + tx * 8 + j0] = o;
        }
    }
}

__global__ __launch_bounds__(256) void gemm_qkv(const float* __restrict__ A,
                                                const float* __restrict__ W,
                                                const float* __restrict__ bias) {
    sgemm_body<MROWS, N3D, DDIM>(A, W, bias, g_qkv);
}

__global__ __launch_bounds__(256) void gemm_proj(const float* __restrict__ W,
                                                 const float* __restrict__ bias,
                                                 float* __restrict__ out) {
    sgemm_body<MROWS, DDIM, DDIM>(g_ao, W, bias, out);
}

// ---------------------------------------------------------------------------
// Flash attention (fp32): one CTA per (b,h, 64-row q tile). 256 threads.
// Q tile [64][64], K^T tile [64][KT_LD] (reused as P), V tile [64][64].
// KT_LD must be a multiple of 4 so float4 accesses stay 16B-aligned.
// Thread (tx,ty) owns a 4x4 microtile: rows ty*4.., cols tx*4..
// ---------------------------------------------------------------------------
#define KT_LD 68
#define ATTN_SMEM ((64 * 64 + 64 * KT_LD + 64 * 64) * 4)

__global__ __launch_bounds__(256) void attn_kernel() {
    extern __shared__ float sm[];
    float* Qs = sm;                    // [64][64]  row-major (row, d)
    float* KP = sm + 64 * 64;          // [64][KT_LD]  K^T (d, j) then P (row, j)
    float* Vs = KP + 64 * KT_LD;       // [64][64]  (j, d)

    const int tid = threadIdx.x;
    const int qt = blockIdx.x;         // q tile index 0..31
    const int bh = blockIdx.y;         // b*H + h
    const int b  = bh >> 4;
    const int h  = bh & 15;

    const int tx  = tid & 15;
    const int ty  = tid >> 4;
    const int tx4 = tx * 4;
    const int ty4 = ty * 4;

    const size_t qrowbase = (size_t)(b * NN + qt * 64);

    // load Q tile (coalesced float4)
    #pragma unroll
    for (int i = 0; i < 4; i++) {
        int r = ty + i * 16;
        float4 v = *(const float4*)&g_qkv[(qrowbase + r) * N3D + h * HD + tx4];
        *(float4*)&Qs[r * 64 + tx4] = v;
    }

    float o[4][4];
    float mrow[4], lrow[4];
    #pragma unroll
    for (int i = 0; i < 4; i++) {
        mrow[i] = -1e30f;
        lrow[i] = 0.f;
        #pragma unroll
        for (int j = 0; j < 4; j++) o[i][j] = 0.f;
    }

    for (int kt = 0; kt <= qt; kt++) {
        __syncthreads();  // prior PV reads of KP/Vs complete

        const size_t krowbase = (size_t)(b * NN + kt * 64);
        // load K tile transposed into KP as K^T[d][j], and V row-major
        #pragma unroll
        for (int i = 0; i < 4; i++) {
            int j = ty + i * 16;
            float4 kv = *(const float4*)&g_qkv[(krowbase + j) * N3D + DDIM + h * HD + tx4];
            KP[(tx4 + 0) * KT_LD + j] = kv.x;
            KP[(tx4 + 1) * KT_LD + j] = kv.y;
            KP[(tx4 + 2) * KT_LD + j] = kv.z;
            KP[(tx4 + 3) * KT_LD + j] = kv.w;
            float4 vv = *(const float4*)&g_qkv[(krowbase + j) * N3D + 2 * DDIM + h * HD + tx4];
            *(float4*)&Vs[j * 64 + tx4] = vv;
        }
        __syncthreads();  // tiles visible

        // S = Q K^T  (4x4 microtile, d unrolled by 4 with float4 smem loads)
        float s[4][4];
        #pragma unroll
        for (int i = 0; i < 4; i++)
            #pragma unroll
            for (int j = 0; j < 4; j++) s[i][j] = 0.f;

        #pragma unroll
        for (int d0 = 0; d0 < 64; d0 += 4) {
            float4 qv[4], kv4[4];
            #pragma unroll
            for (int i = 0; i < 4; i++)
                qv[i] = *(const float4*)&Qs[(ty4 + i) * 64 + d0];
            #pragma unroll
            for (int u = 0; u < 4; u++)
                kv4[u] = *(const float4*)&KP[(d0 + u) * KT_LD + tx4];
            #pragma unroll
            for (int i = 0; i < 4; i++) {
                const float* qp = (const float*)&qv[i];
                #pragma unroll
                for (int u = 0; u < 4; u++) {
                    const float* kp = (const float*)&kv4[u];
                    #pragma unroll
                    for (int j = 0; j < 4; j++)
                        s[i][j] += qp[u] * kp[j];
                }
            }
        }

        // scale + causal mask (only on diagonal tile)
        const bool diag = (kt == qt);
        #pragma unroll
        for (int i = 0; i < 4; i++)
            #pragma unroll
            for (int j = 0; j < 4; j++) {
                float val = s[i][j] * 0.125f;  // HD^-0.5
                if (diag && (tx4 + j > ty4 + i)) val = -1e30f;
                s[i][j] = val;
            }

        __syncthreads();  // all S reads of KP done before overwriting as P

        // online softmax per row; write P into KP
        #pragma unroll
        for (int i = 0; i < 4; i++) {
            float mt = s[i][0];
            mt = fmaxf(mt, s[i][1]);
            mt = fmaxf(mt, s[i][2]);
            mt = fmaxf(mt, s[i][3]);
            #pragma unroll
            for (int off = 8; off >= 1; off >>= 1)
                mt = fmaxf(mt, __shfl_xor_sync(0xffffffffu, mt, off));
            float mnew = fmaxf(mrow[i], mt);
            float corr = __expf(mrow[i] - mnew);
            float lsum = 0.f;
            #pragma unroll
            for (int j = 0; j < 4; j++) {
                float p = __expf(s[i][j] - mnew);
                s[i][j] = p;
                lsum += p;
            }
            #pragma unroll
            for (int off = 8; off >= 1; off >>= 1)
                lsum += __shfl_xor_sync(0xffffffffu, lsum, off);
            lrow[i] = lrow[i] * corr + lsum;
            mrow[i] = mnew;
            #pragma unroll
            for (int d = 0; d < 4; d++) o[i][d] *= corr;
            float4 pv = make_float4(s[i][0], s[i][1], s[i][2], s[i][3]);
            *(float4*)&KP[(ty4 + i) * KT_LD + tx4] = pv;
        }
        __syncthreads();  // P visible

        // O += P @ V
        #pragma unroll
        for (int j0 = 0; j0 < 64; j0 += 4) {
            float4 pr[4], vr[4];
            #pragma unroll
            for (int i = 0; i < 4; i++)
                pr[i] = *(const float4*)&KP[(ty4 + i) * KT_LD + j0];
            #pragma unroll
            for (int u = 0; u < 4; u++)
                vr[u] = *(const float4*)&Vs[(j0 + u) * 64 + tx4];
            #pragma unroll
            for (int i = 0; i < 4; i++) {
                const float* pp = (const float*)&pr[i];
                #pragma unroll
                for (int u = 0; u < 4; u++) {
                    const float* vp = (const float*)&vr[u];
                    #pragma unroll
                    for (int d = 0; d < 4; d++)
                        o[i][d] += pp[u] * vp[d];
                }
            }
        }
    }

    // finalize: divide by l, write to g_ao
    #pragma unroll
    for (int i = 0; i < 4; i++) {
        float inv = 1.0f / lrow[i];
        float4 res = make_float4(o[i][0] * inv, o[i][1] * inv,
                                 o[i][2] * inv, o[i][3] * inv);
        *(float4*)&g_ao[(qrowbase + ty4 + i) * DDIM + h * HD + tx4] = res;
    }
}

// ---------------------------------------------------------------------------
// Launch
// ---------------------------------------------------------------------------
extern "C" void kernel_launch(void* const* d_in, const int* in_sizes, int n_in,
                              void* d_out, int out_size) {
    const float* hs     = (const float*)d_in[0];
    const float* W_attn = (const float*)d_in[1];
    const float* b_attn = (const float*)d_in[2];
    const float* W_proj = (const float*)d_in[3];
    const float* b_proj = (const float*)d_in[4];
    float* out = (float*)d_out;

    cudaFuncSetAttribute(attn_kernel,
                         cudaFuncAttributeMaxDynamicSharedMemorySize, ATTN_SMEM);

    // 1) QKV projection
    dim3 g1(N3D / 128, MROWS / 128);
    gemm_qkv<<<g1, 256>>>(hs, W_attn, b_attn);

    // 2) causal flash attention
    dim3 g2(NN / 64, BB * HH);
    attn_kernel<<<g2, 256, ATTN_SMEM>>>();

    // 3) output projection
    dim3 g3(DDIM / 128, MROWS / 128);
    gemm_proj<<<g3, 256>>>(W_proj, b_proj, out);
}

// round 4
// speedup vs baseline: 1.4317x; 1.4317x over previous
#include <cuda_runtime.h>
#include <cuda_bf16.h>
#include <cstdint>

// Problem constants
#define BB 2
#define NN 2048
#define DDIM 1024
#define HH 16
#define HD 64
#define MROWS (BB * NN)   // 4096
#define N3D (3 * DDIM)    // 3072

// ---------------------------------------------------------------------------
// Scratch (no allocations allowed)
// ---------------------------------------------------------------------------
__device__ __align__(128) float g_qkv[MROWS * N3D];    // [4096, 3072]
__device__ __align__(128) float g_ao[MROWS * DDIM];    // [4096, 1024]
__device__ __align__(128) __nv_bfloat16 g_ahi[MROWS * DDIM];
__device__ __align__(128) __nv_bfloat16 g_alo[MROWS * DDIM];
__device__ __align__(128) __nv_bfloat16 g_aohi[MROWS * DDIM];
__device__ __align__(128) __nv_bfloat16 g_aolo[MROWS * DDIM];
// transposed weights [N, K] K-major
__device__ __align__(128) __nv_bfloat16 g_wqhi[N3D * DDIM];
__device__ __align__(128) __nv_bfloat16 g_wqlo[N3D * DDIM];
__device__ __align__(128) __nv_bfloat16 g_wphi[DDIM * DDIM];
__device__ __align__(128) __nv_bfloat16 g_wplo[DDIM * DDIM];

// ---------------------------------------------------------------------------
// Baseline-PTX tensor-core helpers (ldmatrix + mma.sync, sm_80 baseline)
// ---------------------------------------------------------------------------
__device__ __forceinline__ uint32_t smem_u32(const void* p) {
    uint32_t a;
    asm("{ .reg .u64 t; cvta.to.shared.u64 t, %1; cvt.u32.u64 %0, t; }"
        : "=r"(a) : "l"(p));
    return a;
}

__device__ __forceinline__ void ldsm4(uint32_t r[4], uint32_t addr) {
    asm volatile("ldmatrix.sync.aligned.m8n8.x4.shared.b16 {%0,%1,%2,%3}, [%4];"
                 : "=r"(r[0]), "=r"(r[1]), "=r"(r[2]), "=r"(r[3]) : "r"(addr));
}

__device__ __forceinline__ void mma16816(float c[4], const uint32_t a[4],
                                         uint32_t b0, uint32_t b1) {
    asm volatile(
        "mma.sync.aligned.m16n8k16.row.col.f32.bf16.bf16.f32 "
        "{%0,%1,%2,%3}, {%4,%5,%6,%7}, {%8,%9}, {%0,%1,%2,%3};"
        : "+f"(c[0]), "+f"(c[1]), "+f"(c[2]), "+f"(c[3])
        : "r"(a[0]), "r"(a[1]), "r"(a[2]), "r"(a[3]), "r"(b0), "r"(b1));
}

__device__ __forceinline__ void cp16(uint32_t dst, const void* src) {
    asm volatile("cp.async.cg.shared.global [%0], [%1], 16;"
                 :: "r"(dst), "l"(src) : "memory");
}
#define CP_COMMIT() asm volatile("cp.async.commit_group;" ::: "memory")
#define CP_WAIT1()  asm volatile("cp.async.wait_group 1;" ::: "memory")

// ---------------------------------------------------------------------------
// hi/lo split (elementwise, vectorized)
// ---------------------------------------------------------------------------
__global__ __launch_bounds__(256) void conv_split(const float* __restrict__ x,
                                                  __nv_bfloat16* __restrict__ hi,
                                                  __nv_bfloat16* __restrict__ lo,
                                                  int n4) {
    int i = blockIdx.x * blockDim.x + threadIdx.x;
    if (i >= n4) return;
    float4 v = ((const float4*)x)[i];
    float a[4] = {v.x, v.y, v.z, v.w};
    __nv_bfloat16 h[4], l[4];
    #pragma unroll
    for (int j = 0; j < 4; j++) {
        h[j] = __float2bfloat16(a[j]);
        l[j] = __float2bfloat16(a[j] - __bfloat162float(h[j]));
    }
    ((__nv_bfloat162*)hi)[2 * i]     = __nv_bfloat162(h[0], h[1]);
    ((__nv_bfloat162*)hi)[2 * i + 1] = __nv_bfloat162(h[2], h[3]);
    ((__nv_bfloat162*)lo)[2 * i]     = __nv_bfloat162(l[0], l[1]);
    ((__nv_bfloat162*)lo)[2 * i + 1] = __nv_bfloat162(l[2], l[3]);
}

// Transpose W[K,N] -> out[N,K] with hi/lo split
__global__ __launch_bounds__(256) void transpose_split(const float* __restrict__ W,
                                                       __nv_bfloat16* __restrict__ thi,
                                                       __nv_bfloat16* __restrict__ tlo,
                                                       int K, int N) {
    __shared__ float t[32][33];
    int n0 = blockIdx.x * 32, k0 = blockIdx.y * 32;
    int tx = threadIdx.x, ty = threadIdx.y;  // 32 x 8
    #pragma unroll
    for (int i = 0; i < 4; i++)
        t[ty + i * 8][tx] = W[(size_t)(k0 + ty + i * 8) * N + n0 + tx];
    __syncthreads();
    #pragma unroll
    for (int i = 0; i < 4; i++) {
        int r = ty + i * 8;
        float v = t[tx][r];
        __nv_bfloat16 h = __float2bfloat16(v);
        __nv_bfloat16 l = __float2bfloat16(v - __bfloat162float(h));
        size_t oi = (size_t)(n0 + r) * K + k0 + tx;
        thi[oi] = h;
        tlo[oi] = l;
    }
}

// ---------------------------------------------------------------------------
// bf16x3 GEMM via mma.sync: C[M,NTOT] = A[M,1024] @ B^T + bias, B as [NTOT,1024]
// CTA: 128x128 tile, 256 threads (8 warps, 2x4 warp grid, 64x32 per warp),
// BK=32, 2-stage cp.async pipeline.
// SMEM per stage: 4 tiles of [128][40] bf16 (pad 32->40) = 40960 B. x2 stages.
// ---------------------------------------------------------------------------
#define TILE_B   10240            // one [128][40] bf16 tile
#define STAGE_B  (4 * TILE_B)     // 40960
#define TCG_SMEM (2 * STAGE_B)    // 81920

template<int NTOT>
__global__ __launch_bounds__(256, 1) void tc_gemm(
    const __nv_bfloat16* __restrict__ a_hi, const __nv_bfloat16* __restrict__ a_lo,
    const __nv_bfloat16* __restrict__ b_hi, const __nv_bfloat16* __restrict__ b_lo,
    const float* __restrict__ bias, float* __restrict__ C)
{
    extern __shared__ char sm[];
    const uint32_t smb = smem_u32(sm);
    const int tid = threadIdx.x;
    const int lane = tid & 31;
    const int wid = tid >> 5;
    const int wm = wid & 1;       // 0..1 -> 64-row half
    const int wn = wid >> 1;      // 0..3 -> 32-col quarter
    const int bm = blockIdx.y * 128;
    const int bn = blockIdx.x * 128;

    float acc[4][4][4];
    #pragma unroll
    for (int i = 0; i < 4; i++)
        #pragma unroll
        for (int j = 0; j < 4; j++)
            #pragma unroll
            for (int k = 0; k < 4; k++) acc[i][j][k] = 0.f;

    // --- stage loader: 4 tiles, each thread 2 x 16B per tile ---
    const int lrow = tid >> 2;        // 0..63
    const int lc   = tid & 3;         // 16B chunk in row
    #define LOAD_STAGE(stg, k0)                                                   \
        do {                                                                      \
            uint32_t st_ = smb + (stg) * STAGE_B;                                 \
            _Pragma("unroll")                                                     \
            for (int i_ = 0; i_ < 2; i_++) {                                      \
                int row_ = lrow + i_ * 64;                                        \
                uint32_t doff_ = (uint32_t)(row_ * 80 + lc * 16);                 \
                size_t ga_ = (size_t)(bm + row_) * 1024 + (k0) + lc * 8;          \
                size_t gb_ = (size_t)(bn + row_) * 1024 + (k0) + lc * 8;          \
                cp16(st_ + 0 * TILE_B + doff_, a_hi + ga_);                       \
                cp16(st_ + 1 * TILE_B + doff_, a_lo + ga_);                       \
                cp16(st_ + 2 * TILE_B + doff_, b_hi + gb_);                       \
                cp16(st_ + 3 * TILE_B + doff_, b_lo + gb_);                       \
            }                                                                     \
        } while (0)

    // ldmatrix address components (within a tile, bytes; row stride 80B)
    const uint32_t a_roff = (uint32_t)((wm * 64 + (lane & 15)) * 80 + (lane >> 4) * 16);
    const uint32_t b_row  = (uint32_t)((lane & 7) | ((lane & 16) >> 1));
    const uint32_t b_roff = (uint32_t)((wn * 32 + b_row) * 80 + ((lane >> 3) & 1) * 16);

    LOAD_STAGE(0, 0);
    CP_COMMIT();

    const int NIT = 1024 / 32;  // 32
    for (int it = 0; it < NIT; it++) {
        if (it + 1 < NIT) LOAD_STAGE((it + 1) & 1, (it + 1) * 32);
        CP_COMMIT();
        CP_WAIT1();
        __syncthreads();

        const uint32_t st = smb + (it & 1) * STAGE_B;
        const uint32_t sAh = st, sAl = st + TILE_B, sBh = st + 2 * TILE_B, sBl = st + 3 * TILE_B;

        #pragma unroll
        for (int ks = 0; ks < 2; ks++) {
            uint32_t ah[4][4], al[4][4], bh[2][4], bl[2][4];
            uint32_t ao = a_roff + ks * 32;
            #pragma unroll
            for (int mf = 0; mf < 4; mf++) {
                ldsm4(ah[mf], sAh + ao + mf * 16 * 80);
                ldsm4(al[mf], sAl + ao + mf * 16 * 80);
            }
            uint32_t bo = b_roff + ks * 32;
            #pragma unroll
            for (int g = 0; g < 2; g++) {
                ldsm4(bh[g], sBh + bo + g * 16 * 80);
                ldsm4(bl[g], sBl + bo + g * 16 * 80);
            }
            #pragma unroll
            for (int mf = 0; mf < 4; mf++)
                #pragma unroll
                for (int nf = 0; nf < 4; nf++) {
                    int g = nf >> 1, o = (nf & 1) * 2;
                    mma16816(acc[mf][nf], ah[mf], bh[g][o], bh[g][o + 1]);
                    mma16816(acc[mf][nf], ah[mf], bl[g][o], bl[g][o + 1]);
                    mma16816(acc[mf][nf], al[mf], bh[g][o], bh[g][o + 1]);
                }
        }
        __syncthreads();
    }

    // Epilogue: direct stores with bias
    #pragma unroll
    for (int nf = 0; nf < 4; nf++) {
        int col = bn + wn * 32 + nf * 8 + (lane & 3) * 2;
        float b0 = __ldg(&bias[col]);
        float b1 = __ldg(&bias[col + 1]);
        #pragma unroll
        for (int mf = 0; mf < 4; mf++) {
            int row0 = bm + wm * 64 + mf * 16 + (lane >> 2);
            float2 v0 = make_float2(acc[mf][nf][0] + b0, acc[mf][nf][1] + b1);
            float2 v1 = make_float2(acc[mf][nf][2] + b0, acc[mf][nf][3] + b1);
            *(float2*)&C[(size_t)row0 * NTOT + col]       = v0;
            *(float2*)&C[(size_t)(row0 + 8) * NTOT + col] = v1;
        }
    }
}

// ---------------------------------------------------------------------------
// Flash attention (fp32) — unchanged from round-2 passing version
// ---------------------------------------------------------------------------
#define KT_LD 68
#define ATTN_SMEM ((64 * 64 + 64 * KT_LD + 64 * 64) * 4)

__global__ __launch_bounds__(256) void attn_kernel() {
    extern __shared__ float smf[];
    float* Qs = smf;
    float* KP = smf + 64 * 64;
    float* Vs = KP + 64 * KT_LD;

    const int tid = threadIdx.x;
    const int qt = blockIdx.x;
    const int bh = blockIdx.y;
    const int b  = bh >> 4;
    const int h  = bh & 15;

    const int tx  = tid & 15;
    const int ty  = tid >> 4;
    const int tx4 = tx * 4;
    const int ty4 = ty * 4;

    const size_t qrowbase = (size_t)(b * NN + qt * 64);

    #pragma unroll
    for (int i = 0; i < 4; i++) {
        int r = ty + i * 16;
        float4 v = *(const float4*)&g_qkv[(qrowbase + r) * N3D + h * HD + tx4];
        *(float4*)&Qs[r * 64 + tx4] = v;
    }

    float o[4][4];
    float mrow[4], lrow[4];
    #pragma unroll
    for (int i = 0; i < 4; i++) {
        mrow[i] = -1e30f;
        lrow[i] = 0.f;
        #pragma unroll
        for (int j = 0; j < 4; j++) o[i][j] = 0.f;
    }

    for (int kt = 0; kt <= qt; kt++) {
        __syncthreads();
        const size_t krowbase = (size_t)(b * NN + kt * 64);
        #pragma unroll
        for (int i = 0; i < 4; i++) {
            int j = ty + i * 16;
            float4 kv = *(const float4*)&g_qkv[(krowbase + j) * N3D + DDIM + h * HD + tx4];
            KP[(tx4 + 0) * KT_LD + j] = kv.x;
            KP[(tx4 + 1) * KT_LD + j] = kv.y;
            KP[(tx4 + 2) * KT_LD + j] = kv.z;
            KP[(tx4 + 3) * KT_LD + j] = kv.w;
            float4 vv = *(const float4*)&g_qkv[(krowbase + j) * N3D + 2 * DDIM + h * HD + tx4];
            *(float4*)&Vs[j * 64 + tx4] = vv;
        }
        __syncthreads();

        float s[4][4];
        #pragma unroll
        for (int i = 0; i < 4; i++)
            #pragma unroll
            for (int j = 0; j < 4; j++) s[i][j] = 0.f;

        #pragma unroll
        for (int d0 = 0; d0 < 64; d0 += 4) {
            float4 qv[4], kv4[4];
            #pragma unroll
            for (int i = 0; i < 4; i++)
                qv[i] = *(const float4*)&Qs[(ty4 + i) * 64 + d0];
            #pragma unroll
            for (int u = 0; u < 4; u++)
                kv4[u] = *(const float4*)&KP[(d0 + u) * KT_LD + tx4];
            #pragma unroll
            for (int i = 0; i < 4; i++) {
                const float* qp = (const float*)&qv[i];
                #pragma unroll
                for (int u = 0; u < 4; u++) {
                    const float* kp = (const float*)&kv4[u];
                    #pragma unroll
                    for (int j = 0; j < 4; j++)
                        s[i][j] += qp[u] * kp[j];
                }
            }
        }

        const bool diag = (kt == qt);
        #pragma unroll
        for (int i = 0; i < 4; i++)
            #pragma unroll
            for (int j = 0; j < 4; j++) {
                float val = s[i][j] * 0.125f;
                if (diag && (tx4 + j > ty4 + i)) val = -1e30f;
                s[i][j] = val;
            }

        __syncthreads();

        #pragma unroll
        for (int i = 0; i < 4; i++) {
            float mt = s[i][0];
            mt = fmaxf(mt, s[i][1]);
            mt = fmaxf(mt, s[i][2]);
            mt = fmaxf(mt, s[i][3]);
            #pragma unroll
            for (int off = 8; off >= 1; off >>= 1)
                mt = fmaxf(mt, __shfl_xor_sync(0xffffffffu, mt, off));
            float mnew = fmaxf(mrow[i], mt);
            float corr = __expf(mrow[i] - mnew);
            float lsum = 0.f;
            #pragma unroll
            for (int j = 0; j < 4; j++) {
                float p = __expf(s[i][j] - mnew);
                s[i][j] = p;
                lsum += p;
            }
            #pragma unroll
            for (int off = 8; off >= 1; off >>= 1)
                lsum += __shfl_xor_sync(0xffffffffu, lsum, off);
            lrow[i] = lrow[i] * corr + lsum;
            mrow[i] = mnew;
            #pragma unroll
            for (int d = 0; d < 4; d++) o[i][d] *= corr;
            float4 pv = make_float4(s[i][0], s[i][1], s[i][2], s[i][3]);
            *(float4*)&KP[(ty4 + i) * KT_LD + tx4] = pv;
        }
        __syncthreads();

        #pragma unroll
        for (int j0 = 0; j0 < 64; j0 += 4) {
            float4 pr[4], vr[4];
            #pragma unroll
            for (int i = 0; i < 4; i++)
                pr[i] = *(const float4*)&KP[(ty4 + i) * KT_LD + j0];
            #pragma unroll
            for (int u = 0; u < 4; u++)
                vr[u] = *(const float4*)&Vs[(j0 + u) * 64 + tx4];
            #pragma unroll
            for (int i = 0; i < 4; i++) {
                const float* pp = (const float*)&pr[i];
                #pragma unroll
                for (int u = 0; u < 4; u++) {
                    const float* vp = (const float*)&vr[u];
                    #pragma unroll
                    for (int d = 0; d < 4; d++)
                        o[i][d] += pp[u] * vp[d];
                }
            }
        }
    }

    #pragma unroll
    for (int i = 0; i < 4; i++) {
        float inv = 1.0f / lrow[i];
        float4 res = make_float4(o[i][0] * inv, o[i][1] * inv,
                                 o[i][2] * inv, o[i][3] * inv);
        *(float4*)&g_ao[(qrowbase + ty4 + i) * DDIM + h * HD + tx4] = res;
    }
}

// ---------------------------------------------------------------------------
// Launch
// ---------------------------------------------------------------------------
extern "C" void kernel_launch(void* const* d_in, const int* in_sizes, int n_in,
                              void* d_out, int out_size) {
    const float* hs     = (const float*)d_in[0];
    const float* W_attn = (const float*)d_in[1];
    const float* b_attn = (const float*)d_in[2];
    const float* W_proj = (const float*)d_in[3];
    const float* b_proj = (const float*)d_in[4];
    float* out = (float*)d_out;

    cudaFuncSetAttribute(attn_kernel,
                         cudaFuncAttributeMaxDynamicSharedMemorySize, ATTN_SMEM);
    cudaFuncSetAttribute(tc_gemm<N3D>,
                         cudaFuncAttributeMaxDynamicSharedMemorySize, TCG_SMEM);
    cudaFuncSetAttribute(tc_gemm<DDIM>,
                         cudaFuncAttributeMaxDynamicSharedMemorySize, TCG_SMEM);

    __nv_bfloat16 *ahi, *alo, *aohi, *aolo, *wqhi, *wqlo, *wphi, *wplo;
    float *qkv_p, *ao_p;
    cudaGetSymbolAddress((void**)&ahi,  g_ahi);
    cudaGetSymbolAddress((void**)&alo,  g_alo);
    cudaGetSymbolAddress((void**)&aohi, g_aohi);
    cudaGetSymbolAddress((void**)&aolo, g_aolo);
    cudaGetSymbolAddress((void**)&wqhi, g_wqhi);
    cudaGetSymbolAddress((void**)&wqlo, g_wqlo);
    cudaGetSymbolAddress((void**)&wphi, g_wphi);
    cudaGetSymbolAddress((void**)&wplo, g_wplo);
    cudaGetSymbolAddress((void**)&qkv_p, g_qkv);
    cudaGetSymbolAddress((void**)&ao_p,  g_ao);

    // 1) split hidden_states
    conv_split<<<(MROWS * DDIM / 4 + 255) / 256, 256>>>(hs, ahi, alo, MROWS * DDIM / 4);
    // 2) transpose+split weights
    dim3 tt(32, 8);
    transpose_split<<<dim3(N3D / 32, DDIM / 32), tt>>>(W_attn, wqhi, wqlo, DDIM, N3D);
    transpose_split<<<dim3(DDIM / 32, DDIM / 32), tt>>>(W_proj, wphi, wplo, DDIM, DDIM);
    // 3) QKV projection (tensor cores via mma.sync)
    tc_gemm<N3D><<<dim3(N3D / 128, MROWS / 128), 256, TCG_SMEM>>>(
        ahi, alo, wqhi, wqlo, b_attn, qkv_p);
    // 4) causal flash attention
    attn_kernel<<<dim3(NN / 64, BB * HH), 256, ATTN_SMEM>>>();
    // 5) split attention output
    conv_split<<<(MROWS * DDIM / 4 + 255) / 256, 256>>>(ao_p, aohi, aolo, MROWS * DDIM / 4);
    // 6) output projection (tensor cores via mma.sync)
    tc_gemm<DDIM><<<dim3(DDIM / 128, MROWS / 128), 256, TCG_SMEM>>>(
        aohi, aolo, wphi, wplo, b_proj, out);
}

// round 5
// speedup vs baseline: 2.4489x; 1.7105x over previous
#include <cuda_runtime.h>
#include <cuda_bf16.h>
#include <cstdint>

// Problem constants
#define BB 2
#define NN 2048
#define DDIM 1024
#define HH 16
#define HD 64
#define MROWS (BB * NN)   // 4096
#define N3D (3 * DDIM)    // 3072

// ---------------------------------------------------------------------------
// Scratch (no allocations allowed)
// ---------------------------------------------------------------------------
__device__ __align__(128) float g_qkv[MROWS * N3D];    // [4096, 3072]
__device__ __align__(128) float g_ao[MROWS * DDIM];    // [4096, 1024]
__device__ __align__(128) __nv_bfloat16 g_ahi[MROWS * DDIM];   // hs hi -> later q hi (head-major)
__device__ __align__(128) __nv_bfloat16 g_alo[MROWS * DDIM];   // hs lo -> later q lo
__device__ __align__(128) __nv_bfloat16 g_aohi[MROWS * DDIM];  // k hi (head-major) -> later ao hi
__device__ __align__(128) __nv_bfloat16 g_aolo[MROWS * DDIM];  // k lo -> later ao lo
__device__ __align__(128) __nv_bfloat16 g_vth[MROWS * DDIM];   // V^T hi [bh][64][2048]
__device__ __align__(128) __nv_bfloat16 g_vtl[MROWS * DDIM];   // V^T lo
// transposed weights [N, K] K-major
__device__ __align__(128) __nv_bfloat16 g_wqhi[N3D * DDIM];
__device__ __align__(128) __nv_bfloat16 g_wqlo[N3D * DDIM];
__device__ __align__(128) __nv_bfloat16 g_wphi[DDIM * DDIM];
__device__ __align__(128) __nv_bfloat16 g_wplo[DDIM * DDIM];

// ---------------------------------------------------------------------------
// Baseline-PTX tensor-core helpers
// ---------------------------------------------------------------------------
__device__ __forceinline__ uint32_t smem_u32(const void* p) {
    uint32_t a;
    asm("{ .reg .u64 t; cvta.to.shared.u64 t, %1; cvt.u32.u64 %0, t; }"
        : "=r"(a) : "l"(p));
    return a;
}
__device__ __forceinline__ void ldsm4(uint32_t r[4], uint32_t addr) {
    asm volatile("ldmatrix.sync.aligned.m8n8.x4.shared.b16 {%0,%1,%2,%3}, [%4];"
                 : "=r"(r[0]), "=r"(r[1]), "=r"(r[2]), "=r"(r[3]) : "r"(addr));
}
__device__ __forceinline__ void mma16816(float c[4], const uint32_t a[4],
                                         uint32_t b0, uint32_t b1) {
    asm volatile(
        "mma.sync.aligned.m16n8k16.row.col.f32.bf16.bf16.f32 "
        "{%0,%1,%2,%3}, {%4,%5,%6,%7}, {%8,%9}, {%0,%1,%2,%3};"
        : "+f"(c[0]), "+f"(c[1]), "+f"(c[2]), "+f"(c[3])
        : "r"(a[0]), "r"(a[1]), "r"(a[2]), "r"(a[3]), "r"(b0), "r"(b1));
}
__device__ __forceinline__ void cp16(uint32_t dst, const void* src) {
    asm volatile("cp.async.cg.shared.global [%0], [%1], 16;"
                 :: "r"(dst), "l"(src) : "memory");
}
#define CP_COMMIT() asm volatile("cp.async.commit_group;" ::: "memory")
#define CP_WAIT1()  asm volatile("cp.async.wait_group 1;" ::: "memory")

__device__ __forceinline__ uint32_t packbf(float x, float y) {
    __nv_bfloat162 t = __floats2bfloat162_rn(x, y);
    return *(uint32_t*)&t;
}

// ---------------------------------------------------------------------------
// hi/lo split of hidden states (elementwise)
// ---------------------------------------------------------------------------
__global__ __launch_bounds__(256) void conv_split(const float* __restrict__ x,
                                                  __nv_bfloat16* __restrict__ hi,
                                                  __nv_bfloat16* __restrict__ lo,
                                                  int n4) {
    int i = blockIdx.x * blockDim.x + threadIdx.x;
    if (i >= n4) return;
    float4 v = ((const float4*)x)[i];
    float a[4] = {v.x, v.y, v.z, v.w};
    __nv_bfloat16 h[4], l[4];
    #pragma unroll
    for (int j = 0; j < 4; j++) {
        h[j] = __float2bfloat16(a[j]);
        l[j] = __float2bfloat16(a[j] - __bfloat162float(h[j]));
    }
    ((__nv_bfloat162*)hi)[2 * i]     = __nv_bfloat162(h[0], h[1]);
    ((__nv_bfloat162*)hi)[2 * i + 1] = __nv_bfloat162(h[2], h[3]);
    ((__nv_bfloat162*)lo)[2 * i]     = __nv_bfloat162(l[0], l[1]);
    ((__nv_bfloat162*)lo)[2 * i + 1] = __nv_bfloat162(l[2], l[3]);
}

// Transpose W[K,N] -> out[N,K] with hi/lo split
__global__ __launch_bounds__(256) void transpose_split(const float* __restrict__ W,
                                                       __nv_bfloat16* __restrict__ thi,
                                                       __nv_bfloat16* __restrict__ tlo,
                                                       int K, int N) {
    __shared__ float t[32][33];
    int n0 = blockIdx.x * 32, k0 = blockIdx.y * 32;
    int tx = threadIdx.x, ty = threadIdx.y;  // 32 x 8
    #pragma unroll
    for (int i = 0; i < 4; i++)
        t[ty + i * 8][tx] = W[(size_t)(k0 + ty + i * 8) * N + n0 + tx];
    __syncthreads();
    #pragma unroll
    for (int i = 0; i < 4; i++) {
        int r = ty + i * 8;
        float v = t[tx][r];
        __nv_bfloat16 h = __float2bfloat16(v);
        __nv_bfloat16 l = __float2bfloat16(v - __bfloat162float(h));
        size_t oi = (size_t)(n0 + r) * K + k0 + tx;
        thi[oi] = h;
        tlo[oi] = l;
    }
}

// ---------------------------------------------------------------------------
// Q/K repack: g_qkv -> head-major [bh][n][64] bf16 hi/lo. Q scaled by 0.125.
// ---------------------------------------------------------------------------
__global__ __launch_bounds__(256) void qk_split(
    __nv_bfloat16* __restrict__ qh, __nv_bfloat16* __restrict__ ql,
    __nv_bfloat16* __restrict__ kh, __nv_bfloat16* __restrict__ kl) {
    int i = blockIdx.x * blockDim.x + threadIdx.x;  // over MROWS*1024/4
    if (i >= MROWS * DDIM / 4) return;
    int row = i >> 8;           // 0..4095 (b*2048+n)
    int c4  = i & 255;
    int h   = c4 >> 4;
    int d   = (c4 & 15) * 4;
    int b = row >> 11, n = row & 2047;
    size_t oi = ((size_t)(b * HH + h) * NN + n) * HD + d;

    float4 q = *(const float4*)&g_qkv[(size_t)row * N3D + c4 * 4];
    float4 k = *(const float4*)&g_qkv[(size_t)row * N3D + DDIM + c4 * 4];
    float qa[4] = {q.x * 0.125f, q.y * 0.125f, q.z * 0.125f, q.w * 0.125f};
    float ka[4] = {k.x, k.y, k.z, k.w};
    __nv_bfloat16 qhh[4], qll[4], khh[4], kll[4];
    #pragma unroll
    for (int j = 0; j < 4; j++) {
        qhh[j] = __float2bfloat16(qa[j]);
        qll[j] = __float2bfloat16(qa[j] - __bfloat162float(qhh[j]));
        khh[j] = __float2bfloat16(ka[j]);
        kll[j] = __float2bfloat16(ka[j] - __bfloat162float(khh[j]));
    }
    ((__nv_bfloat162*)(qh + oi))[0] = __nv_bfloat162(qhh[0], qhh[1]);
    ((__nv_bfloat162*)(qh + oi))[1] = __nv_bfloat162(qhh[2], qhh[3]);
    ((__nv_bfloat162*)(ql + oi))[0] = __nv_bfloat162(qll[0], qll[1]);
    ((__nv_bfloat162*)(ql + oi))[1] = __nv_bfloat162(qll[2], qll[3]);
    ((__nv_bfloat162*)(kh + oi))[0] = __nv_bfloat162(khh[0], khh[1]);
    ((__nv_bfloat162*)(kh + oi))[1] = __nv_bfloat162(khh[2], khh[3]);
    ((__nv_bfloat162*)(kl + oi))[0] = __nv_bfloat162(kll[0], kll[1]);
    ((__nv_bfloat162*)(kl + oi))[1] = __nv_bfloat162(kll[2], kll[3]);
}

// ---------------------------------------------------------------------------
// V repack transposed: g_qkv v-part -> [bh][64 d][2048 n] bf16 hi/lo
// One CTA per (bh, 64-row n tile).
// ---------------------------------------------------------------------------
__global__ __launch_bounds__(256) void v_splitT(
    __nv_bfloat16* __restrict__ vth, __nv_bfloat16* __restrict__ vtl) {
    __shared__ float t[64][65];
    const int n0 = blockIdx.x * 64;
    const int bh = blockIdx.y;
    const int b = bh >> 4, h = bh & 15;
    const int tid = threadIdx.x;
    const int r16 = tid >> 4;   // 0..15
    const int c16 = tid & 15;

    #pragma unroll
    for (int i = 0; i < 4; i++) {
        int n = i * 16 + r16;
        float4 v = *(const float4*)&g_qkv[(size_t)(b * NN + n0 + n) * N3D
                                          + 2 * DDIM + h * HD + c16 * 4];
        t[n][c16 * 4 + 0] = v.x;
        t[n][c16 * 4 + 1] = v.y;
        t[n][c16 * 4 + 2] = v.z;
        t[n][c16 * 4 + 3] = v.w;
    }
    __syncthreads();
    #pragma unroll
    for (int i = 0; i < 4; i++) {
        int d = i * 16 + r16;
        int n = c16 * 4;
        __nv_bfloat16 hh[4], ll[4];
        #pragma unroll
        for (int j = 0; j < 4; j++) {
            float v = t[n + j][d];
            hh[j] = __float2bfloat16(v);
            ll[j] = __float2bfloat16(v - __bfloat162float(hh[j]));
        }
        size_t oi = ((size_t)bh * HD + d) * NN + n0 + n;
        ((__nv_bfloat162*)(vth + oi))[0] = __nv_bfloat162(hh[0], hh[1]);
        ((__nv_bfloat162*)(vth + oi))[1] = __nv_bfloat162(hh[2], hh[3]);
        ((__nv_bfloat162*)(vtl + oi))[0] = __nv_bfloat162(ll[0], ll[1]);
        ((__nv_bfloat162*)(vtl + oi))[1] = __nv_bfloat162(ll[2], ll[3]);
    }
}

// ---------------------------------------------------------------------------
// bf16x3 GEMM via mma.sync (unchanged from round 4, passing)
// ---------------------------------------------------------------------------
#define TILE_B   10240
#define STAGE_B  (4 * TILE_B)
#define TCG_SMEM (2 * STAGE_B)

template<int NTOT>
__global__ __launch_bounds__(256, 1) void tc_gemm(
    const __nv_bfloat16* __restrict__ a_hi, const __nv_bfloat16* __restrict__ a_lo,
    const __nv_bfloat16* __restrict__ b_hi, const __nv_bfloat16* __restrict__ b_lo,
    const float* __restrict__ bias, float* __restrict__ C)
{
    extern __shared__ char sm[];
    const uint32_t smb = smem_u32(sm);
    const int tid = threadIdx.x;
    const int lane = tid & 31;
    const int wid = tid >> 5;
    const int wm = wid & 1;
    const int wn = wid >> 1;
    const int bm = blockIdx.y * 128;
    const int bn = blockIdx.x * 128;

    float acc[4][4][4];
    #pragma unroll
    for (int i = 0; i < 4; i++)
        #pragma unroll
        for (int j = 0; j < 4; j++)
            #pragma unroll
            for (int k = 0; k < 4; k++) acc[i][j][k] = 0.f;

    const int lrow = tid >> 2;
    const int lc   = tid & 3;
    #define LOAD_STAGE(stg, k0)                                                   \
        do {                                                                      \
            uint32_t st_ = smb + (stg) * STAGE_B;                                 \
            _Pragma("unroll")                                                     \
            for (int i_ = 0; i_ < 2; i_++) {                                      \
                int row_ = lrow + i_ * 64;                                        \
                uint32_t doff_ = (uint32_t)(row_ * 80 + lc * 16);                 \
                size_t ga_ = (size_t)(bm + row_) * 1024 + (k0) + lc * 8;          \
                size_t gb_ = (size_t)(bn + row_) * 1024 + (k0) + lc * 8;          \
                cp16(st_ + 0 * TILE_B + doff_, a_hi + ga_);                       \
                cp16(st_ + 1 * TILE_B + doff_, a_lo + ga_);                       \
                cp16(st_ + 2 * TILE_B + doff_, b_hi + gb_);                       \
                cp16(st_ + 3 * TILE_B + doff_, b_lo + gb_);                       \
            }                                                                     \
        } while (0)

    const uint32_t a_roff = (uint32_t)((wm * 64 + (lane & 15)) * 80 + (lane >> 4) * 16);
    const uint32_t b_row  = (uint32_t)((lane & 7) | ((lane & 16) >> 1));
    const uint32_t b_roff = (uint32_t)((wn * 32 + b_row) * 80 + ((lane >> 3) & 1) * 16);

    LOAD_STAGE(0, 0);
    CP_COMMIT();

    const int NIT = 1024 / 32;
    for (int it = 0; it < NIT; it++) {
        if (it + 1 < NIT) LOAD_STAGE((it + 1) & 1, (it + 1) * 32);
        CP_COMMIT();
        CP_WAIT1();
        __syncthreads();

        const uint32_t st = smb + (it & 1) * STAGE_B;
        const uint32_t sAh = st, sAl = st + TILE_B, sBh = st + 2 * TILE_B, sBl = st + 3 * TILE_B;

        #pragma unroll
        for (int ks = 0; ks < 2; ks++) {
            uint32_t ah[4][4], al[4][4], bh[2][4], bl[2][4];
            uint32_t ao = a_roff + ks * 32;
            #pragma unroll
            for (int mf = 0; mf < 4; mf++) {
                ldsm4(ah[mf], sAh + ao + mf * 16 * 80);
                ldsm4(al[mf], sAl + ao + mf * 16 * 80);
            }
            uint32_t bo = b_roff + ks * 32;
            #pragma unroll
            for (int g = 0; g < 2; g++) {
                ldsm4(bh[g], sBh + bo + g * 16 * 80);
                ldsm4(bl[g], sBl + bo + g * 16 * 80);
            }
            #pragma unroll
            for (int mf = 0; mf < 4; mf++)
                #pragma unroll
                for (int nf = 0; nf < 4; nf++) {
                    int g = nf >> 1, o = (nf & 1) * 2;
                    mma16816(acc[mf][nf], ah[mf], bh[g][o], bh[g][o + 1]);
                    mma16816(acc[mf][nf], ah[mf], bl[g][o], bl[g][o + 1]);
                    mma16816(acc[mf][nf], al[mf], bh[g][o], bh[g][o + 1]);
                }
        }
        __syncthreads();
    }

    #pragma unroll
    for (int nf = 0; nf < 4; nf++) {
        int col = bn + wn * 32 + nf * 8 + (lane & 3) * 2;
        float b0 = __ldg(&bias[col]);
        float b1 = __ldg(&bias[col + 1]);
        #pragma unroll
        for (int mf = 0; mf < 4; mf++) {
            int row0 = bm + wm * 64 + mf * 16 + (lane >> 2);
            float2 v0 = make_float2(acc[mf][nf][0] + b0, acc[mf][nf][1] + b1);
            float2 v1 = make_float2(acc[mf][nf][2] + b0, acc[mf][nf][3] + b1);
            *(float2*)&C[(size_t)row0 * NTOT + col]       = v0;
            *(float2*)&C[(size_t)(row0 + 8) * NTOT + col] = v1;
        }
    }
}

// ---------------------------------------------------------------------------
// Flash attention via mma.sync, bf16x3 split everywhere.
// CTA = (q-tile of 128 rows, bh). 8 warps x 16 rows. KV tiles of 128.
// Q,K tiles [128][72] bf16 (144B rows), V^T tiles [64][136] bf16 (272B rows).
// ---------------------------------------------------------------------------
#define AT_KSTR 72
#define AT_VSTR 136
#define ATT_SMEM ((2 * 128 * AT_KSTR + 2 * 64 * AT_VSTR) * 2)  // 71680

__global__ __launch_bounds__(256, 1) void attn_mma(
    const __nv_bfloat16* __restrict__ qh, const __nv_bfloat16* __restrict__ ql,
    const __nv_bfloat16* __restrict__ kh, const __nv_bfloat16* __restrict__ kl,
    const __nv_bfloat16* __restrict__ vth, const __nv_bfloat16* __restrict__ vtl)
{
    extern __shared__ __nv_bfloat16 sb[];
    __nv_bfloat16* sKh = sb;
    __nv_bfloat16* sKl = sb + 128 * AT_KSTR;
    __nv_bfloat16* sVh = sb + 2 * 128 * AT_KSTR;
    __nv_bfloat16* sVl = sVh + 64 * AT_VSTR;
    const uint32_t aKh = smem_u32(sKh), aKl = smem_u32(sKl);
    const uint32_t aVh = smem_u32(sVh), aVl = smem_u32(sVl);

    const int tid = threadIdx.x, lane = tid & 31, w = tid >> 5;
    const int qt = 15 - (int)blockIdx.x;     // heavy tiles first
    const int bh = blockIdx.y;
    const int b = bh >> 4, h = bh & 15;
    const size_t hb = (size_t)bh * (NN * HD);   // q/k head base
    const size_t vb = (size_t)bh * (HD * NN);   // v^T head base

    const int r8  = tid >> 3, c8 = tid & 7;     // K/Q tile loaders
    const int r16v = tid >> 4, c16v = tid & 15; // V tile loaders
    const uint32_t brow = (uint32_t)((lane & 7) | ((lane & 16) >> 1));
    const uint32_t bcol8 = (uint32_t)(((lane >> 3) & 1) * 8);

    // ---- stage Q into K buffers, extract A-frags ----
    #pragma unroll
    for (int i = 0; i < 4; i++) {
        int r = i * 32 + r8;
        size_t g = hb + (size_t)(qt * 128 + r) * HD + c8 * 8;
        *(uint4*)(sKh + r * AT_KSTR + c8 * 8) = *(const uint4*)(qh + g);
        *(uint4*)(sKl + r * AT_KSTR + c8 * 8) = *(const uint4*)(ql + g);
    }
    __syncthreads();
    uint32_t qfh[4][4], qfl[4][4];
    #pragma unroll
    for (int ks = 0; ks < 4; ks++) {
        uint32_t off = (uint32_t)(((w * 16 + (lane & 15)) * AT_KSTR
                                   + (lane >> 4) * 8 + ks * 16) * 2);
        ldsm4(qfh[ks], aKh + off);
        ldsm4(qfl[ks], aKl + off);
    }

    float m0 = -1e30f, m1 = -1e30f, l0 = 0.f, l1 = 0.f;
    float o[8][4];
    #pragma unroll
    for (int i = 0; i < 8; i++)
        #pragma unroll
        for (int j = 0; j < 4; j++) o[i][j] = 0.f;

    const int nkv = qt + 1;
    for (int kt = 0; kt < nkv; kt++) {
        __syncthreads();   // previous iter's ldsm reads done (also covers Q extract)
        const int kv0 = kt * 128;
        #pragma unroll
        for (int i = 0; i < 4; i++) {
            int r = i * 32 + r8;
            size_t g = hb + (size_t)(kv0 + r) * HD + c8 * 8;
            *(uint4*)(sKh + r * AT_KSTR + c8 * 8) = *(const uint4*)(kh + g);
            *(uint4*)(sKl + r * AT_KSTR + c8 * 8) = *(const uint4*)(kl + g);
        }
        #pragma unroll
        for (int i = 0; i < 4; i++) {
            int d = i * 16 + r16v;
            size_t g = vb + (size_t)d * NN + kv0 + c16v * 8;
            *(uint4*)(sVh + d * AT_VSTR + c16v * 8) = *(const uint4*)(vth + g);
            *(uint4*)(sVl + d * AT_VSTR + c16v * 8) = *(const uint4*)(vtl + g);
        }
        __syncthreads();

        // ---- S = Q K^T (bf16x3) ----
        float s[16][4];
        #pragma unroll
        for (int i = 0; i < 16; i++)
            #pragma unroll
            for (int j = 0; j < 4; j++) s[i][j] = 0.f;

        #pragma unroll
        for (int g = 0; g < 8; g++) {
            #pragma unroll
            for (int ks = 0; ks < 4; ks++) {
                uint32_t bhf[4], blf[4];
                uint32_t off = (uint32_t)((((g * 16) + brow) * AT_KSTR
                                           + bcol8 + ks * 16) * 2);
                ldsm4(bhf, aKh + off);
                ldsm4(blf, aKl + off);
                #pragma unroll
                for (int nf2 = 0; nf2 < 2; nf2++) {
                    int nf = g * 2 + nf2, oo = nf2 * 2;
                    mma16816(s[nf], qfh[ks], bhf[oo], bhf[oo + 1]);
                    mma16816(s[nf], qfh[ks], blf[oo], blf[oo + 1]);
                    mma16816(s[nf], qfl[ks], bhf[oo], bhf[oo + 1]);
                }
            }
        }

        // ---- causal mask on diagonal tile ----
        if (kt == qt) {
            int row0 = w * 16 + (lane >> 2);
            #pragma unroll
            for (int nf = 0; nf < 16; nf++) {
                int col = nf * 8 + (lane & 3) * 2;
                if (col > row0)     s[nf][0] = -1e30f;
                if (col + 1 > row0) s[nf][1] = -1e30f;
                if (col > row0 + 8)     s[nf][2] = -1e30f;
                if (col + 1 > row0 + 8) s[nf][3] = -1e30f;
            }
        }

        // ---- online softmax ----
        float mt0 = -1e30f, mt1 = -1e30f;
        #pragma unroll
        for (int nf = 0; nf < 16; nf++) {
            mt0 = fmaxf(mt0, fmaxf(s[nf][0], s[nf][1]));
            mt1 = fmaxf(mt1, fmaxf(s[nf][2], s[nf][3]));
        }
        mt0 = fmaxf(mt0, __shfl_xor_sync(0xffffffffu, mt0, 1));
        mt0 = fmaxf(mt0, __shfl_xor_sync(0xffffffffu, mt0, 2));
        mt1 = fmaxf(mt1, __shfl_xor_sync(0xffffffffu, mt1, 1));
        mt1 = fmaxf(mt1, __shfl_xor_sync(0xffffffffu, mt1, 2));
        float mn0 = fmaxf(m0, mt0), mn1 = fmaxf(m1, mt1);
        float cr0 = __expf(m0 - mn0), cr1 = __expf(m1 - mn1);
        float rs0 = 0.f, rs1 = 0.f;
        #pragma unroll
        for (int nf = 0; nf < 16; nf++) {
            s[nf][0] = __expf(s[nf][0] - mn0);
            s[nf][1] = __expf(s[nf][1] - mn0);
            s[nf][2] = __expf(s[nf][2] - mn1);
            s[nf][3] = __expf(s[nf][3] - mn1);
            rs0 += s[nf][0] + s[nf][1];
            rs1 += s[nf][2] + s[nf][3];
        }
        rs0 += __shfl_xor_sync(0xffffffffu, rs0, 1);
        rs0 += __shfl_xor_sync(0xffffffffu, rs0, 2);
        rs1 += __shfl_xor_sync(0xffffffffu, rs1, 1);
        rs1 += __shfl_xor_sync(0xffffffffu, rs1, 2);
        l0 = l0 * cr0 + rs0;
        l1 = l1 * cr1 + rs1;
        m0 = mn0; m1 = mn1;
        #pragma unroll
        for (int nf = 0; nf < 8; nf++) {
            o[nf][0] *= cr0; o[nf][1] *= cr0;
            o[nf][2] *= cr1; o[nf][3] *= cr1;
        }

        // ---- O += P V (bf16x3, P packed on the fly) ----
        #pragma unroll
        for (int ks2 = 0; ks2 < 8; ks2++) {
            uint32_t pah[4], pal[4];
            {
                const float* s0 = s[2 * ks2];
                const float* s1 = s[2 * ks2 + 1];
                float h00 = __bfloat162float(__float2bfloat16(s0[0]));
                float h01 = __bfloat162float(__float2bfloat16(s0[1]));
                float h02 = __bfloat162float(__float2bfloat16(s0[2]));
                float h03 = __bfloat162float(__float2bfloat16(s0[3]));
                float h10 = __bfloat162float(__float2bfloat16(s1[0]));
                float h11 = __bfloat162float(__float2bfloat16(s1[1]));
                float h12 = __bfloat162float(__float2bfloat16(s1[2]));
                float h13 = __bfloat162float(__float2bfloat16(s1[3]));
                pah[0] = packbf(h00, h01);
                pah[1] = packbf(h02, h03);
                pah[2] = packbf(h10, h11);
                pah[3] = packbf(h12, h13);
                pal[0] = packbf(s0[0] - h00, s0[1] - h01);
                pal[1] = packbf(s0[2] - h02, s0[3] - h03);
                pal[2] = packbf(s1[0] - h10, s1[1] - h11);
                pal[3] = packbf(s1[2] - h12, s1[3] - h13);
            }
            #pragma unroll
            for (int g = 0; g < 4; g++) {
                uint32_t vhf[4], vlf[4];
                uint32_t off = (uint32_t)((((g * 16) + brow) * AT_VSTR
                                           + bcol8 + ks2 * 16) * 2);
                ldsm4(vhf, aVh + off);
                ldsm4(vlf, aVl + off);
                #pragma unroll
                for (int nf2 = 0; nf2 < 2; nf2++) {
                    int nf = g * 2 + nf2, oo = nf2 * 2;
                    mma16816(o[nf], pah, vhf[oo], vhf[oo + 1]);
                    mma16816(o[nf], pah, vlf[oo], vlf[oo + 1]);
                    mma16816(o[nf], pal, vhf[oo], vhf[oo + 1]);
                }
            }
        }
    }

    // ---- finalize + write [b*2048+n][h*64+d] ----
    float inv0 = 1.f / l0, inv1 = 1.f / l1;
    const int row0 = b * NN + qt * 128 + w * 16 + (lane >> 2);
    #pragma unroll
    for (int nf = 0; nf < 8; nf++) {
        int col = h * HD + nf * 8 + (lane & 3) * 2;
        *(float2*)&g_ao[(size_t)row0 * DDIM + col] =
            make_float2(o[nf][0] * inv0, o[nf][1] * inv0);
        *(float2*)&g_ao[(size_t)(row0 + 8) * DDIM + col] =
            make_float2(o[nf][2] * inv1, o[nf][3] * inv1);
    }
}

// ---------------------------------------------------------------------------
// Launch
// ---------------------------------------------------------------------------
extern "C" void kernel_launch(void* const* d_in, const int* in_sizes, int n_in,
                              void* d_out, int out_size) {
    const float* hs     = (const float*)d_in[0];
    const float* W_attn = (const float*)d_in[1];
    const float* b_attn = (const float*)d_in[2];
    const float* W_proj = (const float*)d_in[3];
    const float* b_proj = (const float*)d_in[4];
    float* out = (float*)d_out;

    cudaFuncSetAttribute(attn_mma,
                         cudaFuncAttributeMaxDynamicSharedMemorySize, ATT_SMEM);
    cudaFuncSetAttribute(tc_gemm<N3D>,
                         cudaFuncAttributeMaxDynamicSharedMemorySize, TCG_SMEM);
    cudaFuncSetAttribute(tc_gemm<DDIM>,
                         cudaFuncAttributeMaxDynamicSharedMemorySize, TCG_SMEM);

    __nv_bfloat16 *ahi, *alo, *aohi, *aolo, *vth, *vtl, *wqhi, *wqlo, *wphi, *wplo;
    float *qkv_p, *ao_p;
    cudaGetSymbolAddress((void**)&ahi,  g_ahi);
    cudaGetSymbolAddress((void**)&alo,  g_alo);
    cudaGetSymbolAddress((void**)&aohi, g_aohi);
    cudaGetSymbolAddress((void**)&aolo, g_aolo);
    cudaGetSymbolAddress((void**)&vth,  g_vth);
    cudaGetSymbolAddress((void**)&vtl,  g_vtl);
    cudaGetSymbolAddress((void**)&wqhi, g_wqhi);
    cudaGetSymbolAddress((void**)&wqlo, g_wqlo);
    cudaGetSymbolAddress((void**)&wphi, g_wphi);
    cudaGetSymbolAddress((void**)&wplo, g_wplo);
    cudaGetSymbolAddress((void**)&qkv_p, g_qkv);
    cudaGetSymbolAddress((void**)&ao_p,  g_ao);

    // 1) split hidden_states
    conv_split<<<(MROWS * DDIM / 4 + 255) / 256, 256>>>(hs, ahi, alo, MROWS * DDIM / 4);
    // 2) transpose+split weights
    dim3 tt(32, 8);
    transpose_split<<<dim3(N3D / 32, DDIM / 32), tt>>>(W_attn, wqhi, wqlo, DDIM, N3D);
    transpose_split<<<dim3(DDIM / 32, DDIM / 32), tt>>>(W_proj, wphi, wplo, DDIM, DDIM);
    // 3) QKV projection
    tc_gemm<N3D><<<dim3(N3D / 128, MROWS / 128), 256, TCG_SMEM>>>(
        ahi, alo, wqhi, wqlo, b_attn, qkv_p);
    // 4) repack q/k (head-major, q pre-scaled) and v (transposed)
    qk_split<<<(MROWS * DDIM / 4 + 255) / 256, 256>>>(ahi, alo, aohi, aolo);
    v_splitT<<<dim3(NN / 64, BB * HH), 256>>>(vth, vtl);
    // 5) causal flash attention on tensor cores
    attn_mma<<<dim3(NN / 128, BB * HH), 256, ATT_SMEM>>>(ahi, alo, aohi, aolo, vth, vtl);
    // 6) split attention output (reuses k buffers)
    conv_split<<<(MROWS * DDIM / 4 + 255) / 256, 256>>>(ao_p, aohi, aolo, MROWS * DDIM / 4);
    // 7) output projection
    tc_gemm<DDIM><<<dim3(DDIM / 128, MROWS / 128), 256, TCG_SMEM>>>(
        aohi, aolo, wphi, wplo, b_proj, out);
}

// round 6
// speedup vs baseline: 2.4695x; 1.0084x over previous
#include <cuda_runtime.h>
#include <cuda_bf16.h>
#include <cstdint>

// Problem constants
#define BB 2
#define NN 2048
#define DDIM 1024
#define HH 16
#define HD 64
#define MROWS (BB * NN)   // 4096
#define N3D (3 * DDIM)    // 3072

// ---------------------------------------------------------------------------
// Scratch (no allocations allowed)
// ---------------------------------------------------------------------------
__device__ __align__(128) float g_qkv[MROWS * N3D];    // [4096, 3072]
__device__ __align__(128) float g_ao[MROWS * DDIM];    // [4096, 1024]
__device__ __align__(128) __nv_bfloat16 g_ahi[MROWS * DDIM];   // hs hi -> later q hi (head-major)
__device__ __align__(128) __nv_bfloat16 g_alo[MROWS * DDIM];   // hs lo -> later q lo
__device__ __align__(128) __nv_bfloat16 g_aohi[MROWS * DDIM];  // k hi (head-major) -> later ao hi
__device__ __align__(128) __nv_bfloat16 g_aolo[MROWS * DDIM];  // k lo -> later ao lo
__device__ __align__(128) __nv_bfloat16 g_vth[MROWS * DDIM];   // V^T hi [bh][64][2048]
__device__ __align__(128) __nv_bfloat16 g_vtl[MROWS * DDIM];   // V^T lo
// transposed weights [N, K] K-major
__device__ __align__(128) __nv_bfloat16 g_wqhi[N3D * DDIM];
__device__ __align__(128) __nv_bfloat16 g_wqlo[N3D * DDIM];
__device__ __align__(128) __nv_bfloat16 g_wphi[DDIM * DDIM];
__device__ __align__(128) __nv_bfloat16 g_wplo[DDIM * DDIM];

// ---------------------------------------------------------------------------
// Baseline-PTX tensor-core helpers
// ---------------------------------------------------------------------------
__device__ __forceinline__ uint32_t smem_u32(const void* p) {
    uint32_t a;
    asm("{ .reg .u64 t; cvta.to.shared.u64 t, %1; cvt.u32.u64 %0, t; }"
        : "=r"(a) : "l"(p));
    return a;
}
__device__ __forceinline__ void ldsm4(uint32_t r[4], uint32_t addr) {
    asm volatile("ldmatrix.sync.aligned.m8n8.x4.shared.b16 {%0,%1,%2,%3}, [%4];"
                 : "=r"(r[0]), "=r"(r[1]), "=r"(r[2]), "=r"(r[3]) : "r"(addr));
}
__device__ __forceinline__ void mma16816(float c[4], const uint32_t a[4],
                                         uint32_t b0, uint32_t b1) {
    asm volatile(
        "mma.sync.aligned.m16n8k16.row.col.f32.bf16.bf16.f32 "
        "{%0,%1,%2,%3}, {%4,%5,%6,%7}, {%8,%9}, {%0,%1,%2,%3};"
        : "+f"(c[0]), "+f"(c[1]), "+f"(c[2]), "+f"(c[3])
        : "r"(a[0]), "r"(a[1]), "r"(a[2]), "r"(a[3]), "r"(b0), "r"(b1));
}
__device__ __forceinline__ void cp16(uint32_t dst, const void* src) {
    asm volatile("cp.async.cg.shared.global [%0], [%1], 16;"
                 :: "r"(dst), "l"(src) : "memory");
}
#define CP_COMMIT() asm volatile("cp.async.commit_group;" ::: "memory")
#define CP_WAIT1()  asm volatile("cp.async.wait_group 1;" ::: "memory")

__device__ __forceinline__ uint32_t packbf(float x, float y) {
    __nv_bfloat162 t = __floats2bfloat162_rn(x, y);
    return *(uint32_t*)&t;
}

// ---------------------------------------------------------------------------
// hi/lo split of hidden states (elementwise)
// ---------------------------------------------------------------------------
__global__ __launch_bounds__(256) void conv_split(const float* __restrict__ x,
                                                  __nv_bfloat16* __restrict__ hi,
                                                  __nv_bfloat16* __restrict__ lo,
                                                  int n4) {
    int i = blockIdx.x * blockDim.x + threadIdx.x;
    if (i >= n4) return;
    float4 v = ((const float4*)x)[i];
    float a[4] = {v.x, v.y, v.z, v.w};
    __nv_bfloat16 h[4], l[4];
    #pragma unroll
    for (int j = 0; j < 4; j++) {
        h[j] = __float2bfloat16(a[j]);
        l[j] = __float2bfloat16(a[j] - __bfloat162float(h[j]));
    }
    ((__nv_bfloat162*)hi)[2 * i]     = __nv_bfloat162(h[0], h[1]);
    ((__nv_bfloat162*)hi)[2 * i + 1] = __nv_bfloat162(h[2], h[3]);
    ((__nv_bfloat162*)lo)[2 * i]     = __nv_bfloat162(l[0], l[1]);
    ((__nv_bfloat162*)lo)[2 * i + 1] = __nv_bfloat162(l[2], l[3]);
}

// Transpose W[K,N] -> out[N,K] with hi/lo split
__global__ __launch_bounds__(256) void transpose_split(const float* __restrict__ W,
                                                       __nv_bfloat16* __restrict__ thi,
                                                       __nv_bfloat16* __restrict__ tlo,
                                                       int K, int N) {
    __shared__ float t[32][33];
    int n0 = blockIdx.x * 32, k0 = blockIdx.y * 32;
    int tx = threadIdx.x, ty = threadIdx.y;  // 32 x 8
    #pragma unroll
    for (int i = 0; i < 4; i++)
        t[ty + i * 8][tx] = W[(size_t)(k0 + ty + i * 8) * N + n0 + tx];
    __syncthreads();
    #pragma unroll
    for (int i = 0; i < 4; i++) {
        int r = ty + i * 8;
        float v = t[tx][r];
        __nv_bfloat16 h = __float2bfloat16(v);
        __nv_bfloat16 l = __float2bfloat16(v - __bfloat162float(h));
        size_t oi = (size_t)(n0 + r) * K + k0 + tx;
        thi[oi] = h;
        tlo[oi] = l;
    }
}

// ---------------------------------------------------------------------------
// Q/K repack: g_qkv -> head-major [bh][n][64] bf16 hi/lo. Q scaled by 0.125.
// ---------------------------------------------------------------------------
__global__ __launch_bounds__(256) void qk_split(
    __nv_bfloat16* __restrict__ qh, __nv_bfloat16* __restrict__ ql,
    __nv_bfloat16* __restrict__ kh, __nv_bfloat16* __restrict__ kl) {
    int i = blockIdx.x * blockDim.x + threadIdx.x;  // over MROWS*1024/4
    if (i >= MROWS * DDIM / 4) return;
    int row = i >> 8;           // 0..4095 (b*2048+n)
    int c4  = i & 255;
    int h   = c4 >> 4;
    int d   = (c4 & 15) * 4;
    int b = row >> 11, n = row & 2047;
    size_t oi = ((size_t)(b * HH + h) * NN + n) * HD + d;

    float4 q = *(const float4*)&g_qkv[(size_t)row * N3D + c4 * 4];
    float4 k = *(const float4*)&g_qkv[(size_t)row * N3D + DDIM + c4 * 4];
    float qa[4] = {q.x * 0.125f, q.y * 0.125f, q.z * 0.125f, q.w * 0.125f};
    float ka[4] = {k.x, k.y, k.z, k.w};
    __nv_bfloat16 qhh[4], qll[4], khh[4], kll[4];
    #pragma unroll
    for (int j = 0; j < 4; j++) {
        qhh[j] = __float2bfloat16(qa[j]);
        qll[j] = __float2bfloat16(qa[j] - __bfloat162float(qhh[j]));
        khh[j] = __float2bfloat16(ka[j]);
        kll[j] = __float2bfloat16(ka[j] - __bfloat162float(khh[j]));
    }
    ((__nv_bfloat162*)(qh + oi))[0] = __nv_bfloat162(qhh[0], qhh[1]);
    ((__nv_bfloat162*)(qh + oi))[1] = __nv_bfloat162(qhh[2], qhh[3]);
    ((__nv_bfloat162*)(ql + oi))[0] = __nv_bfloat162(qll[0], qll[1]);
    ((__nv_bfloat162*)(ql + oi))[1] = __nv_bfloat162(qll[2], qll[3]);
    ((__nv_bfloat162*)(kh + oi))[0] = __nv_bfloat162(khh[0], khh[1]);
    ((__nv_bfloat162*)(kh + oi))[1] = __nv_bfloat162(khh[2], khh[3]);
    ((__nv_bfloat162*)(kl + oi))[0] = __nv_bfloat162(kll[0], kll[1]);
    ((__nv_bfloat162*)(kl + oi))[1] = __nv_bfloat162(kll[2], kll[3]);
}

// ---------------------------------------------------------------------------
// V repack transposed: g_qkv v-part -> [bh][64 d][2048 n] bf16 hi/lo
// ---------------------------------------------------------------------------
__global__ __launch_bounds__(256) void v_splitT(
    __nv_bfloat16* __restrict__ vth, __nv_bfloat16* __restrict__ vtl) {
    __shared__ float t[64][65];
    const int n0 = blockIdx.x * 64;
    const int bh = blockIdx.y;
    const int b = bh >> 4, h = bh & 15;
    const int tid = threadIdx.x;
    const int r16 = tid >> 4;   // 0..15
    const int c16 = tid & 15;

    #pragma unroll
    for (int i = 0; i < 4; i++) {
        int n = i * 16 + r16;
        float4 v = *(const float4*)&g_qkv[(size_t)(b * NN + n0 + n) * N3D
                                          + 2 * DDIM + h * HD + c16 * 4];
        t[n][c16 * 4 + 0] = v.x;
        t[n][c16 * 4 + 1] = v.y;
        t[n][c16 * 4 + 2] = v.z;
        t[n][c16 * 4 + 3] = v.w;
    }
    __syncthreads();
    #pragma unroll
    for (int i = 0; i < 4; i++) {
        int d = i * 16 + r16;
        int n = c16 * 4;
        __nv_bfloat16 hh[4], ll[4];
        #pragma unroll
        for (int j = 0; j < 4; j++) {
            float v = t[n + j][d];
            hh[j] = __float2bfloat16(v);
            ll[j] = __float2bfloat16(v - __bfloat162float(hh[j]));
        }
        size_t oi = ((size_t)bh * HD + d) * NN + n0 + n;
        ((__nv_bfloat162*)(vth + oi))[0] = __nv_bfloat162(hh[0], hh[1]);
        ((__nv_bfloat162*)(vth + oi))[1] = __nv_bfloat162(hh[2], hh[3]);
        ((__nv_bfloat162*)(vtl + oi))[0] = __nv_bfloat162(ll[0], ll[1]);
        ((__nv_bfloat162*)(vtl + oi))[1] = __nv_bfloat162(ll[2], ll[3]);
    }
}

// ---------------------------------------------------------------------------
// bf16x3 GEMM via mma.sync — 3-stage cp.async pipeline, ONE barrier per iter.
// CTA: 128x128 tile, 256 threads (8 warps, 2x4 warp grid, 64x32 per warp), BK=32.
// SMEM per stage: 4 tiles of [128][40] bf16 = 40960 B. x3 stages = 122880 B.
// ---------------------------------------------------------------------------
#define TILE_B   10240
#define STAGE_B  (4 * TILE_B)
#define TCG_SMEM (3 * STAGE_B)   // 122880

template<int NTOT>
__global__ __launch_bounds__(256, 1) void tc_gemm(
    const __nv_bfloat16* __restrict__ a_hi, const __nv_bfloat16* __restrict__ a_lo,
    const __nv_bfloat16* __restrict__ b_hi, const __nv_bfloat16* __restrict__ b_lo,
    const float* __restrict__ bias, float* __restrict__ C)
{
    extern __shared__ char sm[];
    const uint32_t smb = smem_u32(sm);
    const int tid = threadIdx.x;
    const int lane = tid & 31;
    const int wid = tid >> 5;
    const int wm = wid & 1;
    const int wn = wid >> 1;
    const int bm = blockIdx.y * 128;
    const int bn = blockIdx.x * 128;

    float acc[4][4][4];
    #pragma unroll
    for (int i = 0; i < 4; i++)
        #pragma unroll
        for (int j = 0; j < 4; j++)
            #pragma unroll
            for (int k = 0; k < 4; k++) acc[i][j][k] = 0.f;

    const int lrow = tid >> 2;
    const int lc   = tid & 3;
    #define LOAD_STAGE(stg, k0)                                                   \
        do {                                                                      \
            uint32_t st_ = smb + (stg) * STAGE_B;                                 \
            _Pragma("unroll")                                                     \
            for (int i_ = 0; i_ < 2; i_++) {                                      \
                int row_ = lrow + i_ * 64;                                        \
                uint32_t doff_ = (uint32_t)(row_ * 80 + lc * 16);                 \
                size_t ga_ = (size_t)(bm + row_) * 1024 + (k0) + lc * 8;          \
                size_t gb_ = (size_t)(bn + row_) * 1024 + (k0) + lc * 8;          \
                cp16(st_ + 0 * TILE_B + doff_, a_hi + ga_);                       \
                cp16(st_ + 1 * TILE_B + doff_, a_lo + ga_);                       \
                cp16(st_ + 2 * TILE_B + doff_, b_hi + gb_);                       \
                cp16(st_ + 3 * TILE_B + doff_, b_lo + gb_);                       \
            }                                                                     \
        } while (0)

    const uint32_t a_roff = (uint32_t)((wm * 64 + (lane & 15)) * 80 + (lane >> 4) * 16);
    const uint32_t b_row  = (uint32_t)((lane & 7) | ((lane & 16) >> 1));
    const uint32_t b_roff = (uint32_t)((wn * 32 + b_row) * 80 + ((lane >> 3) & 1) * 16);

    // prologue: stages 0 and 1 in flight
    LOAD_STAGE(0, 0);
    CP_COMMIT();
    LOAD_STAGE(1, 32);
    CP_COMMIT();

    const int NIT = 1024 / 32;  // 32
    int stg = 0;
    for (int it = 0; it < NIT; it++) {
        CP_WAIT1();          // stage `it` complete (this thread's groups)
        __syncthreads();     // all threads' stage `it` visible; stage (it+2)%3 free

        // issue next load immediately so it overlaps this iteration's MMAs
        if (it + 2 < NIT) LOAD_STAGE((stg + 2) % 3, (it + 2) * 32);
        CP_COMMIT();         // exactly one group per iteration

        const uint32_t st = smb + stg * STAGE_B;
        const uint32_t sAh = st, sAl = st + TILE_B, sBh = st + 2 * TILE_B, sBl = st + 3 * TILE_B;

        #pragma unroll
        for (int ks = 0; ks < 2; ks++) {
            uint32_t ah[4][4], al[4][4], bh[2][4], bl[2][4];
            uint32_t ao = a_roff + ks * 32;
            #pragma unroll
            for (int mf = 0; mf < 4; mf++) {
                ldsm4(ah[mf], sAh + ao + mf * 16 * 80);
                ldsm4(al[mf], sAl + ao + mf * 16 * 80);
            }
            uint32_t bo = b_roff + ks * 32;
            #pragma unroll
            for (int g = 0; g < 2; g++) {
                ldsm4(bh[g], sBh + bo + g * 16 * 80);
                ldsm4(bl[g], sBl + bo + g * 16 * 80);
            }
            #pragma unroll
            for (int mf = 0; mf < 4; mf++)
                #pragma unroll
                for (int nf = 0; nf < 4; nf++) {
                    int g = nf >> 1, o = (nf & 1) * 2;
                    mma16816(acc[mf][nf], ah[mf], bh[g][o], bh[g][o + 1]);
                    mma16816(acc[mf][nf], ah[mf], bl[g][o], bl[g][o + 1]);
                    mma16816(acc[mf][nf], al[mf], bh[g][o], bh[g][o + 1]);
                }
        }
        stg = (stg + 1) % 3;
    }

    #pragma unroll
    for (int nf = 0; nf < 4; nf++) {
        int col = bn + wn * 32 + nf * 8 + (lane & 3) * 2;
        float b0 = __ldg(&bias[col]);
        float b1 = __ldg(&bias[col + 1]);
        #pragma unroll
        for (int mf = 0; mf < 4; mf++) {
            int row0 = bm + wm * 64 + mf * 16 + (lane >> 2);
            float2 v0 = make_float2(acc[mf][nf][0] + b0, acc[mf][nf][1] + b1);
            float2 v1 = make_float2(acc[mf][nf][2] + b0, acc[mf][nf][3] + b1);
            *(float2*)&C[(size_t)row0 * NTOT + col]       = v0;
            *(float2*)&C[(size_t)(row0 + 8) * NTOT + col] = v1;
        }
    }
}

// ---------------------------------------------------------------------------
// Flash attention via mma.sync, bf16x3 split everywhere (unchanged, passing)
// ---------------------------------------------------------------------------
#define AT_KSTR 72
#define AT_VSTR 136
#define ATT_SMEM ((2 * 128 * AT_KSTR + 2 * 64 * AT_VSTR) * 2)  // 71680

__global__ __launch_bounds__(256, 1) void attn_mma(
    const __nv_bfloat16* __restrict__ qh, const __nv_bfloat16* __restrict__ ql,
    const __nv_bfloat16* __restrict__ kh, const __nv_bfloat16* __restrict__ kl,
    const __nv_bfloat16* __restrict__ vth, const __nv_bfloat16* __restrict__ vtl)
{
    extern __shared__ __nv_bfloat16 sb[];
    __nv_bfloat16* sKh = sb;
    __nv_bfloat16* sKl = sb + 128 * AT_KSTR;
    __nv_bfloat16* sVh = sb + 2 * 128 * AT_KSTR;
    __nv_bfloat16* sVl = sVh + 64 * AT_VSTR;
    const uint32_t aKh = smem_u32(sKh), aKl = smem_u32(sKl);
    const uint32_t aVh = smem_u32(sVh), aVl = smem_u32(sVl);

    const int tid = threadIdx.x, lane = tid & 31, w = tid >> 5;
    const int qt = 15 - (int)blockIdx.x;
    const int bh = blockIdx.y;
    const int b = bh >> 4, h = bh & 15;
    const size_t hb = (size_t)bh * (NN * HD);
    const size_t vb = (size_t)bh * (HD * NN);

    const int r8  = tid >> 3, c8 = tid & 7;
    const int r16v = tid >> 4, c16v = tid & 15;
    const uint32_t brow = (uint32_t)((lane & 7) | ((lane & 16) >> 1));
    const uint32_t bcol8 = (uint32_t)(((lane >> 3) & 1) * 8);

    #pragma unroll
    for (int i = 0; i < 4; i++) {
        int r = i * 32 + r8;
        size_t g = hb + (size_t)(qt * 128 + r) * HD + c8 * 8;
        *(uint4*)(sKh + r * AT_KSTR + c8 * 8) = *(const uint4*)(qh + g);
        *(uint4*)(sKl + r * AT_KSTR + c8 * 8) = *(const uint4*)(ql + g);
    }
    __syncthreads();
    uint32_t qfh[4][4], qfl[4][4];
    #pragma unroll
    for (int ks = 0; ks < 4; ks++) {
        uint32_t off = (uint32_t)(((w * 16 + (lane & 15)) * AT_KSTR
                                   + (lane >> 4) * 8 + ks * 16) * 2);
        ldsm4(qfh[ks], aKh + off);
        ldsm4(qfl[ks], aKl + off);
    }

    float m0 = -1e30f, m1 = -1e30f, l0 = 0.f, l1 = 0.f;
    float o[8][4];
    #pragma unroll
    for (int i = 0; i < 8; i++)
        #pragma unroll
        for (int j = 0; j < 4; j++) o[i][j] = 0.f;

    const int nkv = qt + 1;
    for (int kt = 0; kt < nkv; kt++) {
        __syncthreads();
        const int kv0 = kt * 128;
        #pragma unroll
        for (int i = 0; i < 4; i++) {
            int r = i * 32 + r8;
            size_t g = hb + (size_t)(kv0 + r) * HD + c8 * 8;
            *(uint4*)(sKh + r * AT_KSTR + c8 * 8) = *(const uint4*)(kh + g);
            *(uint4*)(sKl + r * AT_KSTR + c8 * 8) = *(const uint4*)(kl + g);
        }
        #pragma unroll
        for (int i = 0; i < 4; i++) {
            int d = i * 16 + r16v;
            size_t g = vb + (size_t)d * NN + kv0 + c16v * 8;
            *(uint4*)(sVh + d * AT_VSTR + c16v * 8) = *(const uint4*)(vth + g);
            *(uint4*)(sVl + d * AT_VSTR + c16v * 8) = *(const uint4*)(vtl + g);
        }
        __syncthreads();

        float s[16][4];
        #pragma unroll
        for (int i = 0; i < 16; i++)
            #pragma unroll
            for (int j = 0; j < 4; j++) s[i][j] = 0.f;

        #pragma unroll
        for (int g = 0; g < 8; g++) {
            #pragma unroll
            for (int ks = 0; ks < 4; ks++) {
                uint32_t bhf[4], blf[4];
                uint32_t off = (uint32_t)((((g * 16) + brow) * AT_KSTR
                                           + bcol8 + ks * 16) * 2);
                ldsm4(bhf, aKh + off);
                ldsm4(blf, aKl + off);
                #pragma unroll
                for (int nf2 = 0; nf2 < 2; nf2++) {
                    int nf = g * 2 + nf2, oo = nf2 * 2;
                    mma16816(s[nf], qfh[ks], bhf[oo], bhf[oo + 1]);
                    mma16816(s[nf], qfh[ks], blf[oo], blf[oo + 1]);
                    mma16816(s[nf], qfl[ks], bhf[oo], bhf[oo + 1]);
                }
            }
        }

        if (kt == qt) {
            int row0 = w * 16 + (lane >> 2);
            #pragma unroll
            for (int nf = 0; nf < 16; nf++) {
                int col = nf * 8 + (lane & 3) * 2;
                if (col > row0)     s[nf][0] = -1e30f;
                if (col + 1 > row0) s[nf][1] = -1e30f;
                if (col > row0 + 8)     s[nf][2] = -1e30f;
                if (col + 1 > row0 + 8) s[nf][3] = -1e30f;
            }
        }

        float mt0 = -1e30f, mt1 = -1e30f;
        #pragma unroll
        for (int nf = 0; nf < 16; nf++) {
            mt0 = fmaxf(mt0, fmaxf(s[nf][0], s[nf][1]));
            mt1 = fmaxf(mt1, fmaxf(s[nf][2], s[nf][3]));
        }
        mt0 = fmaxf(mt0, __shfl_xor_sync(0xffffffffu, mt0, 1));
        mt0 = fmaxf(mt0, __shfl_xor_sync(0xffffffffu, mt0, 2));
        mt1 = fmaxf(mt1, __shfl_xor_sync(0xffffffffu, mt1, 1));
        mt1 = fmaxf(mt1, __shfl_xor_sync(0xffffffffu, mt1, 2));
        float mn0 = fmaxf(m0, mt0), mn1 = fmaxf(m1, mt1);
        float cr0 = __expf(m0 - mn0), cr1 = __expf(m1 - mn1);
        float rs0 = 0.f, rs1 = 0.f;
        #pragma unroll
        for (int nf = 0; nf < 16; nf++) {
            s[nf][0] = __expf(s[nf][0] - mn0);
            s[nf][1] = __expf(s[nf][1] - mn0);
            s[nf][2] = __expf(s[nf][2] - mn1);
            s[nf][3] = __expf(s[nf][3] - mn1);
            rs0 += s[nf][0] + s[nf][1];
            rs1 += s[nf][2] + s[nf][3];
        }
        rs0 += __shfl_xor_sync(0xffffffffu, rs0, 1);
        rs0 += __shfl_xor_sync(0xffffffffu, rs0, 2);
        rs1 += __shfl_xor_sync(0xffffffffu, rs1, 1);
        rs1 += __shfl_xor_sync(0xffffffffu, rs1, 2);
        l0 = l0 * cr0 + rs0;
        l1 = l1 * cr1 + rs1;
        m0 = mn0; m1 = mn1;
        #pragma unroll
        for (int nf = 0; nf < 8; nf++) {
            o[nf][0] *= cr0; o[nf][1] *= cr0;
            o[nf][2] *= cr1; o[nf][3] *= cr1;
        }

        #pragma unroll
        for (int ks2 = 0; ks2 < 8; ks2++) {
            uint32_t pah[4], pal[4];
            {
                const float* s0 = s[2 * ks2];
                const float* s1 = s[2 * ks2 + 1];
                float h00 = __bfloat162float(__float2bfloat16(s0[0]));
                float h01 = __bfloat162float(__float2bfloat16(s0[1]));
                float h02 = __bfloat162float(__float2bfloat16(s0[2]));
                float h03 = __bfloat162float(__float2bfloat16(s0[3]));
                float h10 = __bfloat162float(__float2bfloat16(s1[0]));
                float h11 = __bfloat162float(__float2bfloat16(s1[1]));
                float h12 = __bfloat162float(__float2bfloat16(s1[2]));
                float h13 = __bfloat162float(__float2bfloat16(s1[3]));
                pah[0] = packbf(h00, h01);
                pah[1] = packbf(h02, h03);
                pah[2] = packbf(h10, h11);
                pah[3] = packbf(h12, h13);
                pal[0] = packbf(s0[0] - h00, s0[1] - h01);
                pal[1] = packbf(s0[2] - h02, s0[3] - h03);
                pal[2] = packbf(s1[0] - h10, s1[1] - h11);
                pal[3] = packbf(s1[2] - h12, s1[3] - h13);
            }
            #pragma unroll
            for (int g = 0; g < 4; g++) {
                uint32_t vhf[4], vlf[4];
                uint32_t off = (uint32_t)((((g * 16) + brow) * AT_VSTR
                                           + bcol8 + ks2 * 16) * 2);
                ldsm4(vhf, aVh + off);
                ldsm4(vlf, aVl + off);
                #pragma unroll
                for (int nf2 = 0; nf2 < 2; nf2++) {
                    int nf = g * 2 + nf2, oo = nf2 * 2;
                    mma16816(o[nf], pah, vhf[oo], vhf[oo + 1]);
                    mma16816(o[nf], pah, vlf[oo], vlf[oo + 1]);
                    mma16816(o[nf], pal, vhf[oo], vhf[oo + 1]);
                }
            }
        }
    }

    float inv0 = 1.f / l0, inv1 = 1.f / l1;
    const int row0 = b * NN + qt * 128 + w * 16 + (lane >> 2);
    #pragma unroll
    for (int nf = 0; nf < 8; nf++) {
        int col = h * HD + nf * 8 + (lane & 3) * 2;
        *(float2*)&g_ao[(size_t)row0 * DDIM + col] =
            make_float2(o[nf][0] * inv0, o[nf][1] * inv0);
        *(float2*)&g_ao[(size_t)(row0 + 8) * DDIM + col] =
            make_float2(o[nf][2] * inv1, o[nf][3] * inv1);
    }
}

// ---------------------------------------------------------------------------
// Launch
// ---------------------------------------------------------------------------
extern "C" void kernel_launch(void* const* d_in, const int* in_sizes, int n_in,
                              void* d_out, int out_size) {
    const float* hs     = (const float*)d_in[0];
    const float* W_attn = (const float*)d_in[1];
    const float* b_attn = (const float*)d_in[2];
    const float* W_proj = (const float*)d_in[3];
    const float* b_proj = (const float*)d_in[4];
    float* out = (float*)d_out;

    cudaFuncSetAttribute(attn_mma,
                         cudaFuncAttributeMaxDynamicSharedMemorySize, ATT_SMEM);
    cudaFuncSetAttribute(tc_gemm<N3D>,
                         cudaFuncAttributeMaxDynamicSharedMemorySize, TCG_SMEM);
    cudaFuncSetAttribute(tc_gemm<DDIM>,
                         cudaFuncAttributeMaxDynamicSharedMemorySize, TCG_SMEM);

    __nv_bfloat16 *ahi, *alo, *aohi, *aolo, *vth, *vtl, *wqhi, *wqlo, *wphi, *wplo;
    float *qkv_p, *ao_p;
    cudaGetSymbolAddress((void**)&ahi,  g_ahi);
    cudaGetSymbolAddress((void**)&alo,  g_alo);
    cudaGetSymbolAddress((void**)&aohi, g_aohi);
    cudaGetSymbolAddress((void**)&aolo, g_aolo);
    cudaGetSymbolAddress((void**)&vth,  g_vth);
    cudaGetSymbolAddress((void**)&vtl,  g_vtl);
    cudaGetSymbolAddress((void**)&wqhi, g_wqhi);
    cudaGetSymbolAddress((void**)&wqlo, g_wqlo);
    cudaGetSymbolAddress((void**)&wphi, g_wphi);
    cudaGetSymbolAddress((void**)&wplo, g_wplo);
    cudaGetSymbolAddress((void**)&qkv_p, g_qkv);
    cudaGetSymbolAddress((void**)&ao_p,  g_ao);

    // 1) split hidden_states
    conv_split<<<(MROWS * DDIM / 4 + 255) / 256, 256>>>(hs, ahi, alo, MROWS * DDIM / 4);
    // 2) transpose+split weights
    dim3 tt(32, 8);
    transpose_split<<<dim3(N3D / 32, DDIM / 32), tt>>>(W_attn, wqhi, wqlo, DDIM, N3D);
    transpose_split<<<dim3(DDIM / 32, DDIM / 32), tt>>>(W_proj, wphi, wplo, DDIM, DDIM);
    // 3) QKV projection
    tc_gemm<N3D><<<dim3(N3D / 128, MROWS / 128), 256, TCG_SMEM>>>(
        ahi, alo, wqhi, wqlo, b_attn, qkv_p);
    // 4) repack q/k (head-major, q pre-scaled) and v (transposed)
    qk_split<<<(MROWS * DDIM / 4 + 255) / 256, 256>>>(ahi, alo, aohi, aolo);
    v_splitT<<<dim3(NN / 64, BB * HH), 256>>>(vth, vtl);
    // 5) causal flash attention on tensor cores
    attn_mma<<<dim3(NN / 128, BB * HH), 256, ATT_SMEM>>>(ahi, alo, aohi, aolo, vth, vtl);
    // 6) split attention output (reuses k buffers)
    conv_split<<<(MROWS * DDIM / 4 + 255) / 256, 256>>>(ao_p, aohi, aolo, MROWS * DDIM / 4);
    // 7) output projection
    tc_gemm<DDIM><<<dim3(DDIM / 128, MROWS / 128), 256, TCG_SMEM>>>(
        aohi, aolo, wphi, wplo, b_proj, out);
}

// round 7
// speedup vs baseline: 2.5197x; 1.0203x over previous
#include <cuda_runtime.h>
#include <cuda_bf16.h>
#include <cstdint>

// Problem constants
#define BB 2
#define NN 2048
#define DDIM 1024
#define HH 16
#define HD 64
#define MROWS (BB * NN)   // 4096
#define N3D (3 * DDIM)    // 3072

// ---------------------------------------------------------------------------
// Scratch (no allocations allowed)
// ---------------------------------------------------------------------------
__device__ __align__(128) float g_qkv[MROWS * N3D];    // [4096, 3072]
__device__ __align__(128) float g_ao[MROWS * DDIM];    // [4096, 1024]
__device__ __align__(128) __nv_bfloat16 g_ahi[MROWS * DDIM];   // hs hi -> later q hi (head-major)
__device__ __align__(128) __nv_bfloat16 g_alo[MROWS * DDIM];   // hs lo -> later q lo
__device__ __align__(128) __nv_bfloat16 g_aohi[MROWS * DDIM];  // k hi (head-major) -> later ao hi
__device__ __align__(128) __nv_bfloat16 g_aolo[MROWS * DDIM];  // k lo -> later ao lo
__device__ __align__(128) __nv_bfloat16 g_vth[MROWS * DDIM];   // V^T hi [bh][64][2048]
__device__ __align__(128) __nv_bfloat16 g_vtl[MROWS * DDIM];   // V^T lo
// transposed weights [N, K] K-major
__device__ __align__(128) __nv_bfloat16 g_wqhi[N3D * DDIM];
__device__ __align__(128) __nv_bfloat16 g_wqlo[N3D * DDIM];
__device__ __align__(128) __nv_bfloat16 g_wphi[DDIM * DDIM];
__device__ __align__(128) __nv_bfloat16 g_wplo[DDIM * DDIM];

// ---------------------------------------------------------------------------
// Baseline-PTX tensor-core helpers
// ---------------------------------------------------------------------------
__device__ __forceinline__ uint32_t smem_u32(const void* p) {
    uint32_t a;
    asm("{ .reg .u64 t; cvta.to.shared.u64 t, %1; cvt.u32.u64 %0, t; }"
        : "=r"(a) : "l"(p));
    return a;
}
__device__ __forceinline__ void ldsm4(uint32_t r[4], uint32_t addr) {
    asm volatile("ldmatrix.sync.aligned.m8n8.x4.shared.b16 {%0,%1,%2,%3}, [%4];"
                 : "=r"(r[0]), "=r"(r[1]), "=r"(r[2]), "=r"(r[3]) : "r"(addr));
}
__device__ __forceinline__ void mma16816(float c[4], const uint32_t a[4],
                                         uint32_t b0, uint32_t b1) {
    asm volatile(
        "mma.sync.aligned.m16n8k16.row.col.f32.bf16.bf16.f32 "
        "{%0,%1,%2,%3}, {%4,%5,%6,%7}, {%8,%9}, {%0,%1,%2,%3};"
        : "+f"(c[0]), "+f"(c[1]), "+f"(c[2]), "+f"(c[3])
        : "r"(a[0]), "r"(a[1]), "r"(a[2]), "r"(a[3]), "r"(b0), "r"(b1));
}
__device__ __forceinline__ void cp16(uint32_t dst, const void* src) {
    asm volatile("cp.async.cg.shared.global [%0], [%1], 16;"
                 :: "r"(dst), "l"(src) : "memory");
}
#define CP_COMMIT() asm volatile("cp.async.commit_group;" ::: "memory")
#define CP_WAIT1()  asm volatile("cp.async.wait_group 1;" ::: "memory")

__device__ __forceinline__ uint32_t packbf(float x, float y) {
    __nv_bfloat162 t = __floats2bfloat162_rn(x, y);
    return *(uint32_t*)&t;
}

// ---------------------------------------------------------------------------
// hi/lo split of hidden states (elementwise)
// ---------------------------------------------------------------------------
__global__ __launch_bounds__(256) void conv_split(const float* __restrict__ x,
                                                  __nv_bfloat16* __restrict__ hi,
                                                  __nv_bfloat16* __restrict__ lo,
                                                  int n4) {
    int i = blockIdx.x * blockDim.x + threadIdx.x;
    if (i >= n4) return;
    float4 v = ((const float4*)x)[i];
    float a[4] = {v.x, v.y, v.z, v.w};
    __nv_bfloat16 h[4], l[4];
    #pragma unroll
    for (int j = 0; j < 4; j++) {
        h[j] = __float2bfloat16(a[j]);
        l[j] = __float2bfloat16(a[j] - __bfloat162float(h[j]));
    }
    ((__nv_bfloat162*)hi)[2 * i]     = __nv_bfloat162(h[0], h[1]);
    ((__nv_bfloat162*)hi)[2 * i + 1] = __nv_bfloat162(h[2], h[3]);
    ((__nv_bfloat162*)lo)[2 * i]     = __nv_bfloat162(l[0], l[1]);
    ((__nv_bfloat162*)lo)[2 * i + 1] = __nv_bfloat162(l[2], l[3]);
}

// Transpose W[K,N] -> out[N,K] with hi/lo split
__global__ __launch_bounds__(256) void transpose_split(const float* __restrict__ W,
                                                       __nv_bfloat16* __restrict__ thi,
                                                       __nv_bfloat16* __restrict__ tlo,
                                                       int K, int N) {
    __shared__ float t[32][33];
    int n0 = blockIdx.x * 32, k0 = blockIdx.y * 32;
    int tx = threadIdx.x, ty = threadIdx.y;  // 32 x 8
    #pragma unroll
    for (int i = 0; i < 4; i++)
        t[ty + i * 8][tx] = W[(size_t)(k0 + ty + i * 8) * N + n0 + tx];
    __syncthreads();
    #pragma unroll
    for (int i = 0; i < 4; i++) {
        int r = ty + i * 8;
        float v = t[tx][r];
        __nv_bfloat16 h = __float2bfloat16(v);
        __nv_bfloat16 l = __float2bfloat16(v - __bfloat162float(h));
        size_t oi = (size_t)(n0 + r) * K + k0 + tx;
        thi[oi] = h;
        tlo[oi] = l;
    }
}

// ---------------------------------------------------------------------------
// Q/K repack: g_qkv -> head-major [bh][n][64] bf16 hi/lo. Q scaled by 0.125.
// ---------------------------------------------------------------------------
__global__ __launch_bounds__(256) void qk_split(
    __nv_bfloat16* __restrict__ qh, __nv_bfloat16* __restrict__ ql,
    __nv_bfloat16* __restrict__ kh, __nv_bfloat16* __restrict__ kl) {
    int i = blockIdx.x * blockDim.x + threadIdx.x;  // over MROWS*1024/4
    if (i >= MROWS * DDIM / 4) return;
    int row = i >> 8;           // 0..4095 (b*2048+n)
    int c4  = i & 255;
    int h   = c4 >> 4;
    int d   = (c4 & 15) * 4;
    int b = row >> 11, n = row & 2047;
    size_t oi = ((size_t)(b * HH + h) * NN + n) * HD + d;

    float4 q = *(const float4*)&g_qkv[(size_t)row * N3D + c4 * 4];
    float4 k = *(const float4*)&g_qkv[(size_t)row * N3D + DDIM + c4 * 4];
    float qa[4] = {q.x * 0.125f, q.y * 0.125f, q.z * 0.125f, q.w * 0.125f};
    float ka[4] = {k.x, k.y, k.z, k.w};
    __nv_bfloat16 qhh[4], qll[4], khh[4], kll[4];
    #pragma unroll
    for (int j = 0; j < 4; j++) {
        qhh[j] = __float2bfloat16(qa[j]);
        qll[j] = __float2bfloat16(qa[j] - __bfloat162float(qhh[j]));
        khh[j] = __float2bfloat16(ka[j]);
        kll[j] = __float2bfloat16(ka[j] - __bfloat162float(khh[j]));
    }
    ((__nv_bfloat162*)(qh + oi))[0] = __nv_bfloat162(qhh[0], qhh[1]);
    ((__nv_bfloat162*)(qh + oi))[1] = __nv_bfloat162(qhh[2], qhh[3]);
    ((__nv_bfloat162*)(ql + oi))[0] = __nv_bfloat162(qll[0], qll[1]);
    ((__nv_bfloat162*)(ql + oi))[1] = __nv_bfloat162(qll[2], qll[3]);
    ((__nv_bfloat162*)(kh + oi))[0] = __nv_bfloat162(khh[0], khh[1]);
    ((__nv_bfloat162*)(kh + oi))[1] = __nv_bfloat162(khh[2], khh[3]);
    ((__nv_bfloat162*)(kl + oi))[0] = __nv_bfloat162(kll[0], kll[1]);
    ((__nv_bfloat162*)(kl + oi))[1] = __nv_bfloat162(kll[2], kll[3]);
}

// ---------------------------------------------------------------------------
// V repack transposed: g_qkv v-part -> [bh][64 d][2048 n] bf16 hi/lo
// ---------------------------------------------------------------------------
__global__ __launch_bounds__(256) void v_splitT(
    __nv_bfloat16* __restrict__ vth, __nv_bfloat16* __restrict__ vtl) {
    __shared__ float t[64][65];
    const int n0 = blockIdx.x * 64;
    const int bh = blockIdx.y;
    const int b = bh >> 4, h = bh & 15;
    const int tid = threadIdx.x;
    const int r16 = tid >> 4;   // 0..15
    const int c16 = tid & 15;

    #pragma unroll
    for (int i = 0; i < 4; i++) {
        int n = i * 16 + r16;
        float4 v = *(const float4*)&g_qkv[(size_t)(b * NN + n0 + n) * N3D
                                          + 2 * DDIM + h * HD + c16 * 4];
        t[n][c16 * 4 + 0] = v.x;
        t[n][c16 * 4 + 1] = v.y;
        t[n][c16 * 4 + 2] = v.z;
        t[n][c16 * 4 + 3] = v.w;
    }
    __syncthreads();
    #pragma unroll
    for (int i = 0; i < 4; i++) {
        int d = i * 16 + r16;
        int n = c16 * 4;
        __nv_bfloat16 hh[4], ll[4];
        #pragma unroll
        for (int j = 0; j < 4; j++) {
            float v = t[n + j][d];
            hh[j] = __float2bfloat16(v);
            ll[j] = __float2bfloat16(v - __bfloat162float(hh[j]));
        }
        size_t oi = ((size_t)bh * HD + d) * NN + n0 + n;
        ((__nv_bfloat162*)(vth + oi))[0] = __nv_bfloat162(hh[0], hh[1]);
        ((__nv_bfloat162*)(vth + oi))[1] = __nv_bfloat162(hh[2], hh[3]);
        ((__nv_bfloat162*)(vtl + oi))[0] = __nv_bfloat162(ll[0], ll[1]);
        ((__nv_bfloat162*)(vtl + oi))[1] = __nv_bfloat162(ll[2], ll[3]);
    }
}

// ---------------------------------------------------------------------------
// bf16x3 GEMM via mma.sync — 512 threads (16 warps, 4x4 grid, 32x32 per warp).
// 128x128 CTA tile, BK=32, 3-stage cp.async pipeline, one barrier per iter.
// ---------------------------------------------------------------------------
#define TILE_B   10240
#define STAGE_B  (4 * TILE_B)
#define TCG_SMEM (3 * STAGE_B)   // 122880

template<int NTOT>
__global__ __launch_bounds__(512, 1) void tc_gemm(
    const __nv_bfloat16* __restrict__ a_hi, const __nv_bfloat16* __restrict__ a_lo,
    const __nv_bfloat16* __restrict__ b_hi, const __nv_bfloat16* __restrict__ b_lo,
    const float* __restrict__ bias, float* __restrict__ C)
{
    extern __shared__ char sm[];
    const uint32_t smb = smem_u32(sm);
    const int tid = threadIdx.x;
    const int lane = tid & 31;
    const int wid = tid >> 5;
    const int wm = wid & 3;       // 4 row quarters (32 rows each)
    const int wn = wid >> 2;      // 4 col quarters (32 cols each)
    const int bm = blockIdx.y * 128;
    const int bn = blockIdx.x * 128;

    float acc[2][4][4];
    #pragma unroll
    for (int i = 0; i < 2; i++)
        #pragma unroll
        for (int j = 0; j < 4; j++)
            #pragma unroll
            for (int k = 0; k < 4; k++) acc[i][j][k] = 0.f;

    // loader: 512 threads, 1 cp16 per tile each (4 tiles/stage)
    const int lrow = tid >> 2;        // 0..127
    const int lc   = tid & 3;         // 16B chunk in row
    #define LOAD_STAGE(stg, k0)                                                   \
        do {                                                                      \
            uint32_t st_ = smb + (stg) * STAGE_B;                                 \
            uint32_t doff_ = (uint32_t)(lrow * 80 + lc * 16);                     \
            size_t ga_ = (size_t)(bm + lrow) * 1024 + (k0) + lc * 8;              \
            size_t gb_ = (size_t)(bn + lrow) * 1024 + (k0) + lc * 8;              \
            cp16(st_ + 0 * TILE_B + doff_, a_hi + ga_);                           \
            cp16(st_ + 1 * TILE_B + doff_, a_lo + ga_);                           \
            cp16(st_ + 2 * TILE_B + doff_, b_hi + gb_);                           \
            cp16(st_ + 3 * TILE_B + doff_, b_lo + gb_);                           \
        } while (0)

    const uint32_t a_roff = (uint32_t)((wm * 32 + (lane & 15)) * 80 + (lane >> 4) * 16);
    const uint32_t b_row  = (uint32_t)((lane & 7) | ((lane & 16) >> 1));
    const uint32_t b_roff = (uint32_t)((wn * 32 + b_row) * 80 + ((lane >> 3) & 1) * 16);

    LOAD_STAGE(0, 0);
    CP_COMMIT();
    LOAD_STAGE(1, 32);
    CP_COMMIT();

    const int NIT = 1024 / 32;  // 32
    int stg = 0;
    for (int it = 0; it < NIT; it++) {
        CP_WAIT1();
        __syncthreads();

        if (it + 2 < NIT) LOAD_STAGE((stg + 2) % 3, (it + 2) * 32);
        CP_COMMIT();

        const uint32_t st = smb + stg * STAGE_B;
        const uint32_t sAh = st, sAl = st + TILE_B, sBh = st + 2 * TILE_B, sBl = st + 3 * TILE_B;

        #pragma unroll
        for (int ks = 0; ks < 2; ks++) {
            uint32_t ah[2][4], al[2][4], bh[2][4], bl[2][4];
            uint32_t ao = a_roff + ks * 32;
            #pragma unroll
            for (int mf = 0; mf < 2; mf++) {
                ldsm4(ah[mf], sAh + ao + mf * 16 * 80);
                ldsm4(al[mf], sAl + ao + mf * 16 * 80);
            }
            uint32_t bo = b_roff + ks * 32;
            #pragma unroll
            for (int g = 0; g < 2; g++) {
                ldsm4(bh[g], sBh + bo + g * 16 * 80);
                ldsm4(bl[g], sBl + bo + g * 16 * 80);
            }
            #pragma unroll
            for (int mf = 0; mf < 2; mf++)
                #pragma unroll
                for (int nf = 0; nf < 4; nf++) {
                    int g = nf >> 1, o = (nf & 1) * 2;
                    mma16816(acc[mf][nf], ah[mf], bh[g][o], bh[g][o + 1]);
                    mma16816(acc[mf][nf], ah[mf], bl[g][o], bl[g][o + 1]);
                    mma16816(acc[mf][nf], al[mf], bh[g][o], bh[g][o + 1]);
                }
        }
        stg = (stg + 1) % 3;
    }

    #pragma unroll
    for (int nf = 0; nf < 4; nf++) {
        int col = bn + wn * 32 + nf * 8 + (lane & 3) * 2;
        float b0 = __ldg(&bias[col]);
        float b1 = __ldg(&bias[col + 1]);
        #pragma unroll
        for (int mf = 0; mf < 2; mf++) {
            int row0 = bm + wm * 32 + mf * 16 + (lane >> 2);
            float2 v0 = make_float2(acc[mf][nf][0] + b0, acc[mf][nf][1] + b1);
            float2 v1 = make_float2(acc[mf][nf][2] + b0, acc[mf][nf][3] + b1);
            *(float2*)&C[(size_t)row0 * NTOT + col]       = v0;
            *(float2*)&C[(size_t)(row0 + 8) * NTOT + col] = v1;
        }
    }
}

// ---------------------------------------------------------------------------
// Flash attention via mma.sync, bf16x3 split everywhere (unchanged, passing)
// ---------------------------------------------------------------------------
#define AT_KSTR 72
#define AT_VSTR 136
#define ATT_SMEM ((2 * 128 * AT_KSTR + 2 * 64 * AT_VSTR) * 2)  // 71680

__global__ __launch_bounds__(256, 1) void attn_mma(
    const __nv_bfloat16* __restrict__ qh, const __nv_bfloat16* __restrict__ ql,
    const __nv_bfloat16* __restrict__ kh, const __nv_bfloat16* __restrict__ kl,
    const __nv_bfloat16* __restrict__ vth, const __nv_bfloat16* __restrict__ vtl)
{
    extern __shared__ __nv_bfloat16 sb[];
    __nv_bfloat16* sKh = sb;
    __nv_bfloat16* sKl = sb + 128 * AT_KSTR;
    __nv_bfloat16* sVh = sb + 2 * 128 * AT_KSTR;
    __nv_bfloat16* sVl = sVh + 64 * AT_VSTR;
    const uint32_t aKh = smem_u32(sKh), aKl = smem_u32(sKl);
    const uint32_t aVh = smem_u32(sVh), aVl = smem_u32(sVl);

    const int tid = threadIdx.x, lane = tid & 31, w = tid >> 5;
    const int qt = 15 - (int)blockIdx.x;
    const int bh = blockIdx.y;
    const int b = bh >> 4, h = bh & 15;
    const size_t hb = (size_t)bh * (NN * HD);
    const size_t vb = (size_t)bh * (HD * NN);

    const int r8  = tid >> 3, c8 = tid & 7;
    const int r16v = tid >> 4, c16v = tid & 15;
    const uint32_t brow = (uint32_t)((lane & 7) | ((lane & 16) >> 1));
    const uint32_t bcol8 = (uint32_t)(((lane >> 3) & 1) * 8);

    #pragma unroll
    for (int i = 0; i < 4; i++) {
        int r = i * 32 + r8;
        size_t g = hb + (size_t)(qt * 128 + r) * HD + c8 * 8;
        *(uint4*)(sKh + r * AT_KSTR + c8 * 8) = *(const uint4*)(qh + g);
        *(uint4*)(sKl + r * AT_KSTR + c8 * 8) = *(const uint4*)(ql + g);
    }
    __syncthreads();
    uint32_t qfh[4][4], qfl[4][4];
    #pragma unroll
    for (int ks = 0; ks < 4; ks++) {
        uint32_t off = (uint32_t)(((w * 16 + (lane & 15)) * AT_KSTR
                                   + (lane >> 4) * 8 + ks * 16) * 2);
        ldsm4(qfh[ks], aKh + off);
        ldsm4(qfl[ks], aKl + off);
    }

    float m0 = -1e30f, m1 = -1e30f, l0 = 0.f, l1 = 0.f;
    float o[8][4];
    #pragma unroll
    for (int i = 0; i < 8; i++)
        #pragma unroll
        for (int j = 0; j < 4; j++) o[i][j] = 0.f;

    const int nkv = qt + 1;
    for (int kt = 0; kt < nkv; kt++) {
        __syncthreads();
        const int kv0 = kt * 128;
        #pragma unroll
        for (int i = 0; i < 4; i++) {
            int r = i * 32 + r8;
            size_t g = hb + (size_t)(kv0 + r) * HD + c8 * 8;
            *(uint4*)(sKh + r * AT_KSTR + c8 * 8) = *(const uint4*)(kh + g);
            *(uint4*)(sKl + r * AT_KSTR + c8 * 8) = *(const uint4*)(kl + g);
        }
        #pragma unroll
        for (int i = 0; i < 4; i++) {
            int d = i * 16 + r16v;
            size_t g = vb + (size_t)d * NN + kv0 + c16v * 8;
            *(uint4*)(sVh + d * AT_VSTR + c16v * 8) = *(const uint4*)(vth + g);
            *(uint4*)(sVl + d * AT_VSTR + c16v * 8) = *(const uint4*)(vtl + g);
        }
        __syncthreads();

        float s[16][4];
        #pragma unroll
        for (int i = 0; i < 16; i++)
            #pragma unroll
            for (int j = 0; j < 4; j++) s[i][j] = 0.f;

        #pragma unroll
        for (int g = 0; g < 8; g++) {
            #pragma unroll
            for (int ks = 0; ks < 4; ks++) {
                uint32_t bhf[4], blf[4];
                uint32_t off = (uint32_t)((((g * 16) + brow) * AT_KSTR
                                           + bcol8 + ks * 16) * 2);
                ldsm4(bhf, aKh + off);
                ldsm4(blf, aKl + off);
                #pragma unroll
                for (int nf2 = 0; nf2 < 2; nf2++) {
                    int nf = g * 2 + nf2, oo = nf2 * 2;
                    mma16816(s[nf], qfh[ks], bhf[oo], bhf[oo + 1]);
                    mma16816(s[nf], qfh[ks], blf[oo], blf[oo + 1]);
                    mma16816(s[nf], qfl[ks], bhf[oo], bhf[oo + 1]);
                }
            }
        }

        if (kt == qt) {
            int row0 = w * 16 + (lane >> 2);
            #pragma unroll
            for (int nf = 0; nf < 16; nf++) {
                int col = nf * 8 + (lane & 3) * 2;
                if (col > row0)     s[nf][0] = -1e30f;
                if (col + 1 > row0) s[nf][1] = -1e30f;
                if (col > row0 + 8)     s[nf][2] = -1e30f;
                if (col + 1 > row0 + 8) s[nf][3] = -1e30f;
            }
        }

        float mt0 = -1e30f, mt1 = -1e30f;
        #pragma unroll
        for (int nf = 0; nf < 16; nf++) {
            mt0 = fmaxf(mt0, fmaxf(s[nf][0], s[nf][1]));
            mt1 = fmaxf(mt1, fmaxf(s[nf][2], s[nf][3]));
        }
        mt0 = fmaxf(mt0, __shfl_xor_sync(0xffffffffu, mt0, 1));
        mt0 = fmaxf(mt0, __shfl_xor_sync(0xffffffffu, mt0, 2));
        mt1 = fmaxf(mt1, __shfl_xor_sync(0xffffffffu, mt1, 1));
        mt1 = fmaxf(mt1, __shfl_xor_sync(0xffffffffu, mt1, 2));
        float mn0 = fmaxf(m0, mt0), mn1 = fmaxf(m1, mt1);
        float cr0 = __expf(m0 - mn0), cr1 = __expf(m1 - mn1);
        float rs0 = 0.f, rs1 = 0.f;
        #pragma unroll
        for (int nf = 0; nf < 16; nf++) {
            s[nf][0] = __expf(s[nf][0] - mn0);
            s[nf][1] = __expf(s[nf][1] - mn0);
            s[nf][2] = __expf(s[nf][2] - mn1);
            s[nf][3] = __expf(s[nf][3] - mn1);
            rs0 += s[nf][0] + s[nf][1];
            rs1 += s[nf][2] + s[nf][3];
        }
        rs0 += __shfl_xor_sync(0xffffffffu, rs0, 1);
        rs0 += __shfl_xor_sync(0xffffffffu, rs0, 2);
        rs1 += __shfl_xor_sync(0xffffffffu, rs1, 1);
        rs1 += __shfl_xor_sync(0xffffffffu, rs1, 2);
        l0 = l0 * cr0 + rs0;
        l1 = l1 * cr1 + rs1;
        m0 = mn0; m1 = mn1;
        #pragma unroll
        for (int nf = 0; nf < 8; nf++) {
            o[nf][0] *= cr0; o[nf][1] *= cr0;
            o[nf][2] *= cr1; o[nf][3] *= cr1;
        }

        #pragma unroll
        for (int ks2 = 0; ks2 < 8; ks2++) {
            uint32_t pah[4], pal[4];
            {
                const float* s0 = s[2 * ks2];
                const float* s1 = s[2 * ks2 + 1];
                float h00 = __bfloat162float(__float2bfloat16(s0[0]));
                float h01 = __bfloat162float(__float2bfloat16(s0[1]));
                float h02 = __bfloat162float(__float2bfloat16(s0[2]));
                float h03 = __bfloat162float(__float2bfloat16(s0[3]));
                float h10 = __bfloat162float(__float2bfloat16(s1[0]));
                float h11 = __bfloat162float(__float2bfloat16(s1[1]));
                float h12 = __bfloat162float(__float2bfloat16(s1[2]));
                float h13 = __bfloat162float(__float2bfloat16(s1[3]));
                pah[0] = packbf(h00, h01);
                pah[1] = packbf(h02, h03);
                pah[2] = packbf(h10, h11);
                pah[3] = packbf(h12, h13);
                pal[0] = packbf(s0[0] - h00, s0[1] - h01);
                pal[1] = packbf(s0[2] - h02, s0[3] - h03);
                pal[2] = packbf(s1[0] - h10, s1[1] - h11);
                pal[3] = packbf(s1[2] - h12, s1[3] - h13);
            }
            #pragma unroll
            for (int g = 0; g < 4; g++) {
                uint32_t vhf[4], vlf[4];
                uint32_t off = (uint32_t)((((g * 16) + brow) * AT_VSTR
                                           + bcol8 + ks2 * 16) * 2);
                ldsm4(vhf, aVh + off);
                ldsm4(vlf, aVl + off);
                #pragma unroll
                for (int nf2 = 0; nf2 < 2; nf2++) {
                    int nf = g * 2 + nf2, oo = nf2 * 2;
                    mma16816(o[nf], pah, vhf[oo], vhf[oo + 1]);
                    mma16816(o[nf], pah, vlf[oo], vlf[oo + 1]);
                    mma16816(o[nf], pal, vhf[oo], vhf[oo + 1]);
                }
            }
        }
    }

    float inv0 = 1.f / l0, inv1 = 1.f / l1;
    const int row0 = b * NN + qt * 128 + w * 16 + (lane >> 2);
    #pragma unroll
    for (int nf = 0; nf < 8; nf++) {
        int col = h * HD + nf * 8 + (lane & 3) * 2;
        *(float2*)&g_ao[(size_t)row0 * DDIM + col] =
            make_float2(o[nf][0] * inv0, o[nf][1] * inv0);
        *(float2*)&g_ao[(size_t)(row0 + 8) * DDIM + col] =
            make_float2(o[nf][2] * inv1, o[nf][3] * inv1);
    }
}

// ---------------------------------------------------------------------------
// Launch
// ---------------------------------------------------------------------------
extern "C" void kernel_launch(void* const* d_in, const int* in_sizes, int n_in,
                              void* d_out, int out_size) {
    const float* hs     = (const float*)d_in[0];
    const float* W_attn = (const float*)d_in[1];
    const float* b_attn = (const float*)d_in[2];
    const float* W_proj = (const float*)d_in[3];
    const float* b_proj = (const float*)d_in[4];
    float* out = (float*)d_out;

    cudaFuncSetAttribute(attn_mma,
                         cudaFuncAttributeMaxDynamicSharedMemorySize, ATT_SMEM);
    cudaFuncSetAttribute(tc_gemm<N3D>,
                         cudaFuncAttributeMaxDynamicSharedMemorySize, TCG_SMEM);
    cudaFuncSetAttribute(tc_gemm<DDIM>,
                         cudaFuncAttributeMaxDynamicSharedMemorySize, TCG_SMEM);

    __nv_bfloat16 *ahi, *alo, *aohi, *aolo, *vth, *vtl, *wqhi, *wqlo, *wphi, *wplo;
    float *qkv_p, *ao_p;
    cudaGetSymbolAddress((void**)&ahi,  g_ahi);
    cudaGetSymbolAddress((void**)&alo,  g_alo);
    cudaGetSymbolAddress((void**)&aohi, g_aohi);
    cudaGetSymbolAddress((void**)&aolo, g_aolo);
    cudaGetSymbolAddress((void**)&vth,  g_vth);
    cudaGetSymbolAddress((void**)&vtl,  g_vtl);
    cudaGetSymbolAddress((void**)&wqhi, g_wqhi);
    cudaGetSymbolAddress((void**)&wqlo, g_wqlo);
    cudaGetSymbolAddress((void**)&wphi, g_wphi);
    cudaGetSymbolAddress((void**)&wplo, g_wplo);
    cudaGetSymbolAddress((void**)&qkv_p, g_qkv);
    cudaGetSymbolAddress((void**)&ao_p,  g_ao);

    // 1) split hidden_states
    conv_split<<<(MROWS * DDIM / 4 + 255) / 256, 256>>>(hs, ahi, alo, MROWS * DDIM / 4);
    // 2) transpose+split weights
    dim3 tt(32, 8);
    transpose_split<<<dim3(N3D / 32, DDIM / 32), tt>>>(W_attn, wqhi, wqlo, DDIM, N3D);
    transpose_split<<<dim3(DDIM / 32, DDIM / 32), tt>>>(W_proj, wphi, wplo, DDIM, DDIM);
    // 3) QKV projection
    tc_gemm<N3D><<<dim3(N3D / 128, MROWS / 128), 512, TCG_SMEM>>>(
        ahi, alo, wqhi, wqlo, b_attn, qkv_p);
    // 4) repack q/k (head-major, q pre-scaled) and v (transposed)
    qk_split<<<(MROWS * DDIM / 4 + 255) / 256, 256>>>(ahi, alo, aohi, aolo);
    v_splitT<<<dim3(NN / 64, BB * HH), 256>>>(vth, vtl);
    // 5) causal flash attention on tensor cores
    attn_mma<<<dim3(NN / 128, BB * HH), 256, ATT_SMEM>>>(ahi, alo, aohi, aolo, vth, vtl);
    // 6) split attention output (reuses k buffers)
    conv_split<<<(MROWS * DDIM / 4 + 255) / 256, 256>>>(ao_p, aohi, aolo, MROWS * DDIM / 4);
    // 7) output projection
    tc_gemm<DDIM><<<dim3(DDIM / 128, MROWS / 128), 512, TCG_SMEM>>>(
        aohi, aolo, wphi, wplo, b_proj, out);
}